// round 6
// baseline (speedup 1.0000x reference)
#include <cuda_runtime.h>
#include <cstdint>
#include <math.h>

#define Bz     32
#define Nn     100
#define Ff     514
#define FE     614      // 514 feats + 100 mask cols
#define ROWSE  101
#define NN2    10000
#define DIMMAX 10000
#define BLKP   128      // pairs per block in pair kernel
#define PBLK   79       // ceil(DIMMAX/128)

// ---------------- scratch (static device globals; no allocation) ----------------
__device__ int   d_order[Bz * DIMMAX];
__device__ int   d_count[Bz];
__device__ float d_Gg[Bz * 64];
__device__ float d_A[Bz * Nn * 64];
__device__ float d_C[Bz * Nn * 64];
__device__ float d_logit[Bz * DIMMAX];   // holds e = exp(logit - shift)
__device__ float d_sig[Bz * DIMMAX];

// ---------------- small helpers ----------------
__device__ __forceinline__ int read_dim(const int* p) {
    int v = *p;
    if (v < 1 || v > DIMMAX) {            // safety: tolerate float-encoded scalar
        float f = __int_as_float(v);
        v = (int)f;
    }
    if (v < 0) v = 0;
    if (v > DIMMAX) v = DIMMAX;
    return v;
}

__device__ __forceinline__ float my_tanh(float x) {
    // tanh(x) = 1 - 2/(exp(2x)+1)   (exact identity; __expf rel err ~2^-22)
    float e = __expf(2.0f * x);
    return 1.0f - __fdividef(2.0f, e + 1.0f);
}

// ================= prep kernel: fused scan / head / ac via blockIdx.y ===========
// dynamic smem: 20x516 rows tile (41280B) + 32x128 W chunk (16384B) = 57664B

#define PREP_SMEM (41280 + 16384)

__device__ void scan_role(const float* __restrict__ emb, int b, int dim, char* sh) {
    int t = threadIdx.x;           // 256
    int lane = t & 31, w = t >> 5; // 8 warps
    unsigned* bal = (unsigned*)sh;         // [320]
    int* pre = (int*)(sh + 320 * 4);       // [320]
    // phase 1: ballots for 40 chunks of 256
#pragma unroll
    for (int c = 0; c < 40; ++c) {
        int idx = c * 256 + t;
        int flag = 0;
        if (idx < NN2) {
            int i = idx / Nn, j = idx - i * Nn;
            flag = emb[(size_t)(b * ROWSE + 1 + i) * FE + Ff + j] > 0.5f;
        }
        unsigned bl = __ballot_sync(0xffffffffu, flag);
        if (lane == 0) bal[c * 8 + w] = bl;
    }
    __syncthreads();
    // phase 2: warp 0 does exclusive scan over 320 counts (10 per lane)
    if (t < 32) {
        int loc[10];
        int s = 0;
#pragma unroll
        for (int k = 0; k < 10; ++k) {
            int v = __popc(bal[lane * 10 + k]);
            loc[k] = s;
            s += v;
        }
        int p = s;
#pragma unroll
        for (int o = 1; o < 32; o <<= 1) {
            int n = __shfl_up_sync(0xffffffffu, p, o);
            if (lane >= o) p += n;
        }
        int off = p - s;
#pragma unroll
        for (int k = 0; k < 10; ++k) pre[lane * 10 + k] = off + loc[k];
        if (lane == 31) d_count[b] = p;
    }
    __syncthreads();
    // phase 3: write ranks
#pragma unroll
    for (int c = 0; c < 40; ++c) {
        unsigned bl = bal[c * 8 + w];
        if ((bl >> lane) & 1u) {
            int rank = pre[c * 8 + w] + __popc(bl & ((1u << lane) - 1u));
            if (rank < dim) d_order[b * DIMMAX + rank] = c * 256 + t;
        }
    }
}

__device__ void head_role(const float* __restrict__ emb,
                          const float* __restrict__ aw0, const float* __restrict__ ab0,
                          const float* __restrict__ cw0, const float* __restrict__ cb0,
                          const float* __restrict__ cw1, const float* __restrict__ cb1,
                          const float* __restrict__ cw2, const float* __restrict__ cb2,
                          const float* __restrict__ cw3, const float* __restrict__ cb3,
                          float* __restrict__ out, int voff, int b, char* sh) {
    float* row = (float*)sh;              // [516]
    float* part = row + 516;              // [256]
    float* ha = part + 256;               // [64]
    float* hb = ha + 64;                  // [64]
    int t = threadIdx.x;                  // 256
    for (int k = t; k < Ff; k += 256) row[k] = emb[(size_t)b * ROWSE * FE + k];
    __syncthreads();
    int j = t & 63, ks = t >> 6;  // 4-way k split
    {
        float acc = 0.f;
        for (int k = ks; k < Ff; k += 4) acc += row[k] * aw0[(size_t)k * 64 + j];
        part[t] = acc;
    }
    __syncthreads();
    if (t < 64) {
        float s = ab0[j] + part[j] + part[64 + j] + part[128 + j] + part[192 + j];
        d_Gg[b * 64 + j] = s;
    }
    __syncthreads();
    {
        float acc = 0.f;
        for (int k = ks; k < Ff; k += 4) acc += row[k] * cw0[(size_t)k * 64 + j];
        part[t] = acc;
    }
    __syncthreads();
    if (t < 64) {
        float s = cb0[j] + part[j] + part[64 + j] + part[128 + j] + part[192 + j];
        ha[j] = my_tanh(s);
    }
    __syncthreads();
    if (t < 64) {
        float acc = cb1[t];
        for (int k = 0; k < 64; ++k) acc += ha[k] * cw1[k * 64 + t];
        hb[t] = my_tanh(acc);
    }
    __syncthreads();
    if (t < 64) {
        float acc = cb2[t];
        for (int k = 0; k < 64; ++k) acc += hb[k] * cw2[k * 64 + t];
        ha[t] = my_tanh(acc);
    }
    __syncthreads();
    if (t == 0) {
        float v = cb3[0];
        for (int k = 0; k < 64; ++k) v += ha[k] * cw3[k];
        out[voff + b] = v;
    }
}

// A = nodes @ W0[514:1028], C = nodes @ W0[1028:1542]; W staged via smem chunks
__device__ void ac_role(const float* __restrict__ emb, const float* __restrict__ w0,
                        int b, int gy, char* sh) {
    float (*rows)[516] = (float (*)[516])sh;         // 20 x 516
    float* sW = (float*)(sh + 41280);                 // 32 x 128 chunk
    int t = threadIdx.x;          // 256
    int R0 = 1 + gy * 20;
    for (int e = t; e < 20 * Ff; e += 256) {
        int r = e / Ff, k = e - r * Ff;
        rows[r][k] = emb[(size_t)(b * ROWSE + R0 + r) * FE + k];
    }
    int j = t & 127, half = t >> 7;
    const float* wA = w0 + (size_t)Ff * 64;           // A weights [514][64]
    const float* wC = w0 + (size_t)2 * Ff * 64;       // C weights [514][64]
    float acc[10];
#pragma unroll
    for (int rr = 0; rr < 10; ++rr) acc[rr] = 0.f;

    for (int kc = 0; kc < 16; ++kc) {
        int kb = kc * 32;
        __syncthreads();
        // stage W chunk [32][128] coalesced
#pragma unroll
        for (int i = 0; i < 16; ++i) {
            int e = t + 256 * i;
            int k = e >> 7, jj = e & 127;
            int kg = kb + k;
            sW[e] = (jj < 64) ? wA[(size_t)kg * 64 + jj] : wC[(size_t)kg * 64 + (jj - 64)];
        }
        __syncthreads();
#pragma unroll
        for (int kk = 0; kk < 32; kk += 4) {
            float wv0 = sW[(kk + 0) * 128 + j];
            float wv1 = sW[(kk + 1) * 128 + j];
            float wv2 = sW[(kk + 2) * 128 + j];
            float wv3 = sW[(kk + 3) * 128 + j];
#pragma unroll
            for (int rr = 0; rr < 10; ++rr) {
                int r = half + 2 * rr;
                float4 hv = *(const float4*)&rows[r][kb + kk];
                acc[rr] += hv.x * wv0 + hv.y * wv1 + hv.z * wv2 + hv.w * wv3;
            }
        }
    }
    // tail k = 512, 513 (global, scattered but tiny)
    {
        const float* wcol = (j < 64) ? (wA + j) : (wC + (j - 64));
        float wv0 = wcol[(size_t)512 * 64], wv1 = wcol[(size_t)513 * 64];
#pragma unroll
        for (int rr = 0; rr < 10; ++rr) {
            int r = half + 2 * rr;
            acc[rr] += rows[r][512] * wv0 + rows[r][513] * wv1;
        }
    }
#pragma unroll
    for (int rr = 0; rr < 10; ++rr) {
        int node = gy * 20 + half + 2 * rr;
        if (j < 64) d_A[((size_t)(b * Nn + node)) * 64 + j] = acc[rr];
        else        d_C[((size_t)(b * Nn + node)) * 64 + (j - 64)] = acc[rr];
    }
}

__global__ void prep_kernel(const float* __restrict__ emb,
                            const float* __restrict__ aw0, const float* __restrict__ ab0,
                            const float* __restrict__ cw0, const float* __restrict__ cb0,
                            const float* __restrict__ cw1, const float* __restrict__ cb1,
                            const float* __restrict__ cw2, const float* __restrict__ cb2,
                            const float* __restrict__ cw3, const float* __restrict__ cb3,
                            float* __restrict__ out, int voff,
                            const int* __restrict__ dimp) {
    extern __shared__ __align__(16) char sh[];
    int b = blockIdx.x;
    int role = blockIdx.y;
    if (role == 0) {
        scan_role(emb, b, read_dim(dimp), sh);
    } else if (role == 1) {
        head_role(emb, aw0, ab0, cw0, cb0, cw1, cb1, cw2, cb2, cw3, cb3, out, voff, b, sh);
    } else {
        ac_role(emb, aw0, b, role - 2, sh);
    }
}

// ================= pair kernel v5: 128 pairs/block, 256 threads, 8x4 tiles ======
struct PairSmem {
    float Wa1[2048], Wb1[2048];   // layer1 weights, j mod 8 < 4 / >= 4 halves
    float Wa2[2048], Wb2[2048];   // layer2
    float X[64 * 128];            // activations [k][pair], XOR-swizzled 16B groups
    float W3[128];                // [k][2]
    float b1[64], b2[64], b0[64], Gg[64];
    float b3[2];
};
#define PAIR_SMEM_BYTES ((int)sizeof(PairSmem))

// element address in X for (row k, pair p): 16B-group XOR swizzle keyed on (k>>3)&7
__device__ __forceinline__ int xaddr(int k, int p) {
    return k * 128 + ((((p) >> 2) ^ ((k >> 3) & 7)) << 2) + (p & 3);
}

__device__ __forceinline__ void gemm64s(const float* __restrict__ sX,
                                        const float* __restrict__ sWa,
                                        const float* __restrict__ sWb,
                                        const float* __restrict__ sb,
                                        float (&acc)[8][4], int jg, int pg) {
#pragma unroll
    for (int ji = 0; ji < 8; ++ji) {
        float bj = sb[jg * 8 + ji];
#pragma unroll
        for (int pi = 0; pi < 4; ++pi) acc[ji][pi] = bj;
    }
    for (int k8 = 0; k8 < 8; ++k8) {
        const float* xbase = sX + k8 * 8 * 128 + ((pg ^ k8) << 2);
        const float* wa = sWa + k8 * 8 * 32 + jg * 4;
        const float* wb = sWb + k8 * 8 * 32 + jg * 4;
#pragma unroll
        for (int kk = 0; kk < 8; ++kk) {
            float4 a = *(const float4*)(xbase + kk * 128);
            float4 w0 = *(const float4*)(wa + kk * 32);
            float4 w1 = *(const float4*)(wb + kk * 32);
            float as[4] = {a.x, a.y, a.z, a.w};
            float ws[8] = {w0.x, w0.y, w0.z, w0.w, w1.x, w1.y, w1.z, w1.w};
#pragma unroll
            for (int ji = 0; ji < 8; ++ji)
#pragma unroll
                for (int pi = 0; pi < 4; ++pi)
                    acc[ji][pi] += ws[ji] * as[pi];
        }
    }
}

__device__ __forceinline__ void tanh_store(float* __restrict__ sX,
                                           float (&acc)[8][4], int jg, int pg) {
    int g = (pg ^ jg) << 2;
#pragma unroll
    for (int ji = 0; ji < 8; ++ji) {
        int j = jg * 8 + ji;
        float4 v;
        v.x = my_tanh(acc[ji][0]); v.y = my_tanh(acc[ji][1]);
        v.z = my_tanh(acc[ji][2]); v.w = my_tanh(acc[ji][3]);
        *(float4*)(sX + j * 128 + g) = v;
    }
}

__global__ __launch_bounds__(256, 3) void pair_kernel(
    const float* __restrict__ aw1, const float* __restrict__ ab1,
    const float* __restrict__ aw2, const float* __restrict__ ab2,
    const float* __restrict__ aw3, const float* __restrict__ ab3,
    const float* __restrict__ ab0, const int* __restrict__ dimp) {
    extern __shared__ __align__(16) char smem_raw[];
    PairSmem* sm = (PairSmem*)smem_raw;
    int dim = read_dim(dimp);
    int p0 = blockIdx.x * BLKP;
    if (p0 >= dim) return;               // uniform block exit
    int b = blockIdx.y, t = threadIdx.x;

    // ---- stage weights/biases into shared (split-half layout) ----
    {
        const float4* a1v = (const float4*)aw1;
        const float4* a2v = (const float4*)aw2;
#pragma unroll
        for (int it = 0; it < 4; ++it) {
            int g = t + 256 * it;
            int k = g >> 4, gg = g & 15;
            int half = gg & 1, j8 = gg >> 1;
            int di = k * 8 + j8;
            float4 v1 = a1v[g];
            float4 v2 = a2v[g];
            ((float4*)(half ? sm->Wb1 : sm->Wa1))[di] = v1;
            ((float4*)(half ? sm->Wb2 : sm->Wa2))[di] = v2;
        }
        if (t < 64) {
            sm->b1[t] = ab1[t];
            sm->b2[t] = ab2[t];
            sm->b0[t] = ab0[t];
            sm->Gg[t] = d_Gg[b * 64 + t];
            sm->W3[2 * t + 0] = aw3[2 * t + 0];
            sm->W3[2 * t + 1] = aw3[2 * t + 1];
        }
        if (t < 2) sm->b3[t] = ab3[t];
    }
    __syncthreads();

    // shift SA = sum_k |W3[k][0]|  (logit part <= SA since |h| < 1)
    float SA = 0.f;
#pragma unroll
    for (int k = 0; k < 64; ++k) SA += fabsf(sm->W3[2 * k]);

    // ---- layer 0: 2 threads per pair, each builds 32 features ----
    {
        int lp = t >> 1, half = t & 1;
        int p = p0 + lp;
        int cnt = d_count[b];
        int kb = half * 32;
        if (p < cnt && p < dim) {
            int q = d_order[b * DIMMAX + p];
            int i1 = q / Nn, i2 = q - i1 * Nn;
            const float4* Ga = (const float4*)(d_A + ((size_t)(b * Nn + i1)) * 64 + kb);
            const float4* Cc = (const float4*)(d_C + ((size_t)(b * Nn + i2)) * 64 + kb);
#pragma unroll
            for (int kk = 0; kk < 8; ++kk) {
                float4 a = Ga[kk], c = Cc[kk];
                int k = kb + 4 * kk;
                sm->X[xaddr(k + 0, lp)] = my_tanh(sm->Gg[k + 0] + a.x + c.x);
                sm->X[xaddr(k + 1, lp)] = my_tanh(sm->Gg[k + 1] + a.y + c.y);
                sm->X[xaddr(k + 2, lp)] = my_tanh(sm->Gg[k + 2] + a.z + c.z);
                sm->X[xaddr(k + 3, lp)] = my_tanh(sm->Gg[k + 3] + a.w + c.w);
            }
        } else {
            // invalid / out-of-range: zeroed input -> pre-activation = b0
#pragma unroll
            for (int k = kb; k < kb + 32; ++k) sm->X[xaddr(k, lp)] = my_tanh(sm->b0[k]);
        }
    }
    __syncthreads();

    int jg = t & 7, pg = t >> 3;
    float acc[8][4];

    // ---- layer 1 ----
    gemm64s(sm->X, sm->Wa1, sm->Wb1, sm->b1, acc, jg, pg);
    __syncthreads();
    tanh_store(sm->X, acc, jg, pg);
    __syncthreads();

    // ---- layer 2 ----
    gemm64s(sm->X, sm->Wa2, sm->Wb2, sm->b2, acc, jg, pg);
    __syncthreads();
    tanh_store(sm->X, acc, jg, pg);
    __syncthreads();

    // ---- layer 3: 2 threads per pair, shfl-combined (64 -> 2) ----
    {
        int lp = t >> 1, half = t & 1;
        int p = p0 + lp;
        float lg = 0.f, bl = 0.f;
        int kb = half * 32;
#pragma unroll
        for (int kk = 0; kk < 32; ++kk) {
            int k = kb + kk;
            float h = sm->X[xaddr(k, lp)];
            lg += h * sm->W3[2 * k + 0];
            bl += h * sm->W3[2 * k + 1];
        }
        lg += __shfl_xor_sync(0xffffffffu, lg, 1);
        bl += __shfl_xor_sync(0xffffffffu, bl, 1);
        if (half == 0 && p < dim) {
            // e = exp(logit - (b3 + SA)); softmax is shift-invariant
            d_logit[b * DIMMAX + p] = __expf(lg - SA);
            d_sig[b * DIMMAX + p] = 1.0f / (1.0f + __expf(-(bl + sm->b3[1])));
        }
    }
}

// ---------------- kernel 3: zero + sum(e) + scatter (one block per batch) -------
__global__ void softscatter_kernel(float* __restrict__ out, const int* __restrict__ dimp) {
    int b = blockIdx.x, t = threadIdx.x;  // 1024 threads
    int dim = read_dim(dimp);
    __shared__ float red[32];
    __shared__ float sInv;
    float* ob = out + (size_t)b * 20000;
    // zero this batch's output slab
    float4 z4 = make_float4(0.f, 0.f, 0.f, 0.f);
    for (int i = t; i < 5000; i += 1024) ((float4*)ob)[i] = z4;
    // sum of e
    float s = 0.f;
    for (int p = t; p < dim; p += 1024) s += d_logit[b * DIMMAX + p];
#pragma unroll
    for (int o = 16; o; o >>= 1) s += __shfl_xor_sync(0xffffffffu, s, o);
    if ((t & 31) == 0) red[t >> 5] = s;
    __syncthreads();
    if (t == 0) {
        float tot = 0.f;
        for (int i = 0; i < 32; ++i) tot += red[i];
        sInv = 1.0f / tot;
    }
    __syncthreads();
    float inv = sInv;
    int cnt = d_count[b];
    int lim = (cnt < dim) ? cnt : dim;
    for (int p = t; p < lim; p += 1024) {
        int q = d_order[b * DIMMAX + p];
        float pi = d_logit[b * DIMMAX + p] * inv;
        float sg = d_sig[b * DIMMAX + p];
        ob[q] = pi * sg;
        ob[10000 + q] = pi * (1.0f - sg);
    }
}

// ---------------- launcher (3 launches, single stream) ----------------
extern "C" void kernel_launch(void* const* d_in, const int* in_sizes, int n_in,
                              void* d_out, int out_size) {
    const float* emb = (const float*)d_in[0];
    const int* dimp;
    int base;
    if (n_in >= 18 && in_sizes[1] == 1) {   // dict order: emb, dim, actor..., critic...
        dimp = (const int*)d_in[1];
        base = 2;
    } else {                                // signature order: emb, actor..., critic..., dim
        dimp = (const int*)d_in[n_in - 1];
        base = 1;
    }
    const float* aw0 = (const float*)d_in[base + 0];
    const float* ab0 = (const float*)d_in[base + 1];
    const float* aw1 = (const float*)d_in[base + 2];
    const float* ab1 = (const float*)d_in[base + 3];
    const float* aw2 = (const float*)d_in[base + 4];
    const float* ab2 = (const float*)d_in[base + 5];
    const float* aw3 = (const float*)d_in[base + 6];
    const float* ab3 = (const float*)d_in[base + 7];
    const float* cw0 = (const float*)d_in[base + 8];
    const float* cb0 = (const float*)d_in[base + 9];
    const float* cw1 = (const float*)d_in[base + 10];
    const float* cb1 = (const float*)d_in[base + 11];
    const float* cw2 = (const float*)d_in[base + 12];
    const float* cb2 = (const float*)d_in[base + 13];
    const float* cw3 = (const float*)d_in[base + 14];
    const float* cb3 = (const float*)d_in[base + 15];

    float* out = (float*)d_out;
    int voff = out_size - Bz;  // value slot after the filled region (expect 640000)

    static int init_done = 0;
    if (!init_done) {
        cudaFuncSetAttribute(pair_kernel, cudaFuncAttributeMaxDynamicSharedMemorySize,
                             PAIR_SMEM_BYTES);
        cudaFuncSetAttribute(prep_kernel, cudaFuncAttributeMaxDynamicSharedMemorySize,
                             PREP_SMEM);
        init_done = 1;
    }

    prep_kernel<<<dim3(Bz, 7), 256, PREP_SMEM>>>(emb, aw0, ab0, cw0, cb0, cw1, cb1,
                                                 cw2, cb2, cw3, cb3, out, voff, dimp);
    pair_kernel<<<dim3(PBLK, Bz), 256, PAIR_SMEM_BYTES>>>(aw1, ab1, aw2, ab2, aw3, ab3,
                                                          ab0, dimp);
    softscatter_kernel<<<Bz, 1024>>>(out, dimp);
}

// round 7
// speedup vs baseline: 1.0442x; 1.0442x over previous
#include <cuda_runtime.h>
#include <cstdint>
#include <math.h>

#define Bz     32
#define Nn     100
#define Ff     514
#define FE     614      // 514 feats + 100 mask cols
#define ROWSE  101
#define NN2    10000
#define DIMMAX 10000
#define BLKP   128      // pairs per block in pair kernel
#define PBLK   79       // ceil(DIMMAX/128)

// ---------------- scratch (static device globals; no allocation) ----------------
__device__ int   d_order[Bz * DIMMAX];
__device__ int   d_count[Bz];
__device__ float d_Gg[Bz * 64];
__device__ float d_A[Bz * Nn * 64];
__device__ float d_C[Bz * Nn * 64];
__device__ float d_logit[Bz * DIMMAX];   // holds e = exp(logit - shift)
__device__ float d_sig[Bz * DIMMAX];

// ---------------- small helpers ----------------
__device__ __forceinline__ int read_dim(const int* p) {
    int v = *p;
    if (v < 1 || v > DIMMAX) {            // safety: tolerate float-encoded scalar
        float f = __int_as_float(v);
        v = (int)f;
    }
    if (v < 0) v = 0;
    if (v > DIMMAX) v = DIMMAX;
    return v;
}

__device__ __forceinline__ float my_tanh(float x) {
    // tanh(x) = 1 - 2/(exp(2x)+1)   (exact identity; __expf rel err ~2^-22)
    float e = __expf(2.0f * x);
    return 1.0f - __fdividef(2.0f, e + 1.0f);
}

// ================= prep kernel: scan / head / ac(10) / zero via blockIdx.y ======
// dynamic smem: 10x516 rows (20640B) + 2x 32x128 W chunks (32768B) = 53408B
#define PREP_SMEM (20640 + 32768)

__device__ void scan_role(const float* __restrict__ emb, int b, int dim, char* sh) {
    int t = threadIdx.x;           // 256
    int lane = t & 31, w = t >> 5; // 8 warps
    unsigned* bal = (unsigned*)sh;         // [320]
    int* pre = (int*)(sh + 320 * 4);       // [320]
#pragma unroll
    for (int c = 0; c < 40; ++c) {
        int idx = c * 256 + t;
        int flag = 0;
        if (idx < NN2) {
            int i = idx / Nn, j = idx - i * Nn;
            flag = emb[(size_t)(b * ROWSE + 1 + i) * FE + Ff + j] > 0.5f;
        }
        unsigned bl = __ballot_sync(0xffffffffu, flag);
        if (lane == 0) bal[c * 8 + w] = bl;
    }
    __syncthreads();
    if (t < 32) {
        int loc[10];
        int s = 0;
#pragma unroll
        for (int k = 0; k < 10; ++k) {
            int v = __popc(bal[lane * 10 + k]);
            loc[k] = s;
            s += v;
        }
        int p = s;
#pragma unroll
        for (int o = 1; o < 32; o <<= 1) {
            int n = __shfl_up_sync(0xffffffffu, p, o);
            if (lane >= o) p += n;
        }
        int off = p - s;
#pragma unroll
        for (int k = 0; k < 10; ++k) pre[lane * 10 + k] = off + loc[k];
        if (lane == 31) d_count[b] = p;
    }
    __syncthreads();
#pragma unroll
    for (int c = 0; c < 40; ++c) {
        unsigned bl = bal[c * 8 + w];
        if ((bl >> lane) & 1u) {
            int rank = pre[c * 8 + w] + __popc(bl & ((1u << lane) - 1u));
            if (rank < dim) d_order[b * DIMMAX + rank] = c * 256 + t;
        }
    }
}

__device__ void head_role(const float* __restrict__ emb,
                          const float* __restrict__ aw0, const float* __restrict__ ab0,
                          const float* __restrict__ cw0, const float* __restrict__ cb0,
                          const float* __restrict__ cw1, const float* __restrict__ cb1,
                          const float* __restrict__ cw2, const float* __restrict__ cb2,
                          const float* __restrict__ cw3, const float* __restrict__ cb3,
                          float* __restrict__ out, int voff, int b, char* sh) {
    float* row = (float*)sh;              // [516]
    float* part = row + 516;              // [256]
    float* ha = part + 256;               // [64]
    float* hb = ha + 64;                  // [64]
    int t = threadIdx.x;                  // 256
    for (int k = t; k < Ff; k += 256) row[k] = emb[(size_t)b * ROWSE * FE + k];
    __syncthreads();
    int j = t & 63, ks = t >> 6;  // 4-way k split
    {
        float acc = 0.f;
        for (int k = ks; k < Ff; k += 4) acc += row[k] * aw0[(size_t)k * 64 + j];
        part[t] = acc;
    }
    __syncthreads();
    if (t < 64) {
        float s = ab0[j] + part[j] + part[64 + j] + part[128 + j] + part[192 + j];
        d_Gg[b * 64 + j] = s;
    }
    __syncthreads();
    {
        float acc = 0.f;
        for (int k = ks; k < Ff; k += 4) acc += row[k] * cw0[(size_t)k * 64 + j];
        part[t] = acc;
    }
    __syncthreads();
    if (t < 64) {
        float s = cb0[j] + part[j] + part[64 + j] + part[128 + j] + part[192 + j];
        ha[j] = my_tanh(s);
    }
    __syncthreads();
    if (t < 64) {
        float acc = cb1[t];
        for (int k = 0; k < 64; ++k) acc += ha[k] * cw1[k * 64 + t];
        hb[t] = my_tanh(acc);
    }
    __syncthreads();
    if (t < 64) {
        float acc = cb2[t];
        for (int k = 0; k < 64; ++k) acc += hb[k] * cw2[k * 64 + t];
        ha[t] = my_tanh(acc);
    }
    __syncthreads();
    if (t == 0) {
        float v = cb3[0];
        for (int k = 0; k < 64; ++k) v += ha[k] * cw3[k];
        out[voff + b] = v;
    }
}

// A = nodes @ W0[514:1028], C = nodes @ W0[1028:1542]
// 10-node group per block; W staged in double-buffered smem chunks via registers.
__device__ void ac_role(const float* __restrict__ emb, const float* __restrict__ w0,
                        int b, int gy, char* sh) {
    float (*rows)[516] = (float (*)[516])sh;          // 10 x 516
    float* sW = (float*)(sh + 20640);                 // 2 x 4096 floats
    int t = threadIdx.x;          // 256
    int R0 = 1 + gy * 10;
    for (int e = t; e < 10 * Ff; e += 256) {
        int r = e / Ff, k = e - r * Ff;
        rows[r][k] = emb[(size_t)(b * ROWSE + R0 + r) * FE + k];
    }
    int j = t & 127, half = t >> 7;
    const float* wA = w0 + (size_t)Ff * 64;           // A weights [514][64]
    const float* wC = w0 + (size_t)2 * Ff * 64;       // C weights [514][64]

    float reg[16];
#define LOADW(kb)                                                            \
    do {                                                                     \
        _Pragma("unroll") for (int i = 0; i < 16; ++i) {                     \
            int e = t + 256 * i;                                             \
            int k = e >> 7, jj = e & 127;                                    \
            int kg = (kb) + k;                                               \
            reg[i] = (jj < 64) ? wA[(size_t)kg * 64 + jj]                    \
                               : wC[(size_t)kg * 64 + (jj - 64)];            \
        }                                                                    \
    } while (0)

    LOADW(0);
#pragma unroll
    for (int i = 0; i < 16; ++i) sW[t + 256 * i] = reg[i];
    __syncthreads();

    float acc[5];
#pragma unroll
    for (int rr = 0; rr < 5; ++rr) acc[rr] = 0.f;

    for (int kc = 0; kc < 16; ++kc) {
        const float* cur = sW + (kc & 1) * 4096;
        float* alt = sW + ((kc & 1) ^ 1) * 4096;
        if (kc < 15) LOADW((kc + 1) * 32);   // prefetch next chunk into regs
        int kb = kc * 32;
#pragma unroll
        for (int kk = 0; kk < 32; kk += 4) {
            float wv0 = cur[(kk + 0) * 128 + j];
            float wv1 = cur[(kk + 1) * 128 + j];
            float wv2 = cur[(kk + 2) * 128 + j];
            float wv3 = cur[(kk + 3) * 128 + j];
#pragma unroll
            for (int rr = 0; rr < 5; ++rr) {
                int r = half + 2 * rr;
                float4 hv = *(const float4*)&rows[r][kb + kk];
                acc[rr] += hv.x * wv0 + hv.y * wv1 + hv.z * wv2 + hv.w * wv3;
            }
        }
        if (kc < 15) {
#pragma unroll
            for (int i = 0; i < 16; ++i) alt[t + 256 * i] = reg[i];
        }
        __syncthreads();
    }
#undef LOADW
    // tail k = 512, 513
    {
        const float* wcol = (j < 64) ? (wA + j) : (wC + (j - 64));
        float wv0 = wcol[(size_t)512 * 64], wv1 = wcol[(size_t)513 * 64];
#pragma unroll
        for (int rr = 0; rr < 5; ++rr) {
            int r = half + 2 * rr;
            acc[rr] += rows[r][512] * wv0 + rows[r][513] * wv1;
        }
    }
#pragma unroll
    for (int rr = 0; rr < 5; ++rr) {
        int node = gy * 10 + half + 2 * rr;
        if (j < 64) d_A[((size_t)(b * Nn + node)) * 64 + j] = acc[rr];
        else        d_C[((size_t)(b * Nn + node)) * 64 + (j - 64)] = acc[rr];
    }
}

__device__ void zero_role(float* __restrict__ out, int b) {
    float4 z = make_float4(0.f, 0.f, 0.f, 0.f);
    float4* ob = (float4*)(out + (size_t)b * 20000);
    for (int i = threadIdx.x; i < 5000; i += 256) ob[i] = z;
}

__global__ void prep_kernel(const float* __restrict__ emb,
                            const float* __restrict__ aw0, const float* __restrict__ ab0,
                            const float* __restrict__ cw0, const float* __restrict__ cb0,
                            const float* __restrict__ cw1, const float* __restrict__ cb1,
                            const float* __restrict__ cw2, const float* __restrict__ cb2,
                            const float* __restrict__ cw3, const float* __restrict__ cb3,
                            float* __restrict__ out, int voff,
                            const int* __restrict__ dimp) {
    extern __shared__ __align__(16) char sh[];
    int b = blockIdx.x;
    int role = blockIdx.y;
    if (role < 10) {
        ac_role(emb, aw0, b, role, sh);
    } else if (role == 10) {
        scan_role(emb, b, read_dim(dimp), sh);
    } else if (role == 11) {
        head_role(emb, aw0, ab0, cw0, cb0, cw1, cb1, cw2, cb2, cw3, cb3, out, voff, b, sh);
    } else {
        zero_role(out, b);
    }
}

// ================= pair kernel v5: 128 pairs/block, 256 threads, 8x4 tiles ======
struct PairSmem {
    float Wa1[2048], Wb1[2048];   // layer1 weights, j mod 8 < 4 / >= 4 halves
    float Wa2[2048], Wb2[2048];   // layer2
    float X[64 * 128];            // activations [k][pair], XOR-swizzled 16B groups
    float W3[128];                // [k][2]
    float b1[64], b2[64], b0[64], Gg[64];
    float b3[2];
};
#define PAIR_SMEM_BYTES ((int)sizeof(PairSmem))

// element address in X for (row k, pair p): 16B-group XOR swizzle keyed on (k>>3)&7
__device__ __forceinline__ int xaddr(int k, int p) {
    return k * 128 + ((((p) >> 2) ^ ((k >> 3) & 7)) << 2) + (p & 3);
}

__device__ __forceinline__ void gemm64s(const float* __restrict__ sX,
                                        const float* __restrict__ sWa,
                                        const float* __restrict__ sWb,
                                        const float* __restrict__ sb,
                                        float (&acc)[8][4], int jg, int pg) {
#pragma unroll
    for (int ji = 0; ji < 8; ++ji) {
        float bj = sb[jg * 8 + ji];
#pragma unroll
        for (int pi = 0; pi < 4; ++pi) acc[ji][pi] = bj;
    }
    for (int k8 = 0; k8 < 8; ++k8) {
        const float* xbase = sX + k8 * 8 * 128 + ((pg ^ k8) << 2);
        const float* wa = sWa + k8 * 8 * 32 + jg * 4;
        const float* wb = sWb + k8 * 8 * 32 + jg * 4;
#pragma unroll
        for (int kk = 0; kk < 8; ++kk) {
            float4 a = *(const float4*)(xbase + kk * 128);
            float4 w0 = *(const float4*)(wa + kk * 32);
            float4 w1 = *(const float4*)(wb + kk * 32);
            float as[4] = {a.x, a.y, a.z, a.w};
            float ws[8] = {w0.x, w0.y, w0.z, w0.w, w1.x, w1.y, w1.z, w1.w};
#pragma unroll
            for (int ji = 0; ji < 8; ++ji)
#pragma unroll
                for (int pi = 0; pi < 4; ++pi)
                    acc[ji][pi] += ws[ji] * as[pi];
        }
    }
}

__device__ __forceinline__ void tanh_store(float* __restrict__ sX,
                                           float (&acc)[8][4], int jg, int pg) {
    int g = (pg ^ jg) << 2;
#pragma unroll
    for (int ji = 0; ji < 8; ++ji) {
        int j = jg * 8 + ji;
        float4 v;
        v.x = my_tanh(acc[ji][0]); v.y = my_tanh(acc[ji][1]);
        v.z = my_tanh(acc[ji][2]); v.w = my_tanh(acc[ji][3]);
        *(float4*)(sX + j * 128 + g) = v;
    }
}

__global__ __launch_bounds__(256, 3) void pair_kernel(
    const float* __restrict__ aw1, const float* __restrict__ ab1,
    const float* __restrict__ aw2, const float* __restrict__ ab2,
    const float* __restrict__ aw3, const float* __restrict__ ab3,
    const float* __restrict__ ab0, const int* __restrict__ dimp) {
    extern __shared__ __align__(16) char smem_raw[];
    PairSmem* sm = (PairSmem*)smem_raw;
    int dim = read_dim(dimp);
    int p0 = blockIdx.x * BLKP;
    if (p0 >= dim) return;               // uniform block exit
    int b = blockIdx.y, t = threadIdx.x;

    // ---- stage weights/biases into shared (split-half layout) ----
    {
        const float4* a1v = (const float4*)aw1;
        const float4* a2v = (const float4*)aw2;
#pragma unroll
        for (int it = 0; it < 4; ++it) {
            int g = t + 256 * it;
            int k = g >> 4, gg = g & 15;
            int half = gg & 1, j8 = gg >> 1;
            int di = k * 8 + j8;
            float4 v1 = a1v[g];
            float4 v2 = a2v[g];
            ((float4*)(half ? sm->Wb1 : sm->Wa1))[di] = v1;
            ((float4*)(half ? sm->Wb2 : sm->Wa2))[di] = v2;
        }
        if (t < 64) {
            sm->b1[t] = ab1[t];
            sm->b2[t] = ab2[t];
            sm->b0[t] = ab0[t];
            sm->Gg[t] = d_Gg[b * 64 + t];
            sm->W3[2 * t + 0] = aw3[2 * t + 0];
            sm->W3[2 * t + 1] = aw3[2 * t + 1];
        }
        if (t < 2) sm->b3[t] = ab3[t];
    }
    __syncthreads();

    // shift SA = sum_k |W3[k][0]|  (logit part <= SA since |h| < 1)
    float SA = 0.f;
#pragma unroll
    for (int k = 0; k < 64; ++k) SA += fabsf(sm->W3[2 * k]);

    // ---- layer 0: 2 threads per pair, each builds 32 features ----
    {
        int lp = t >> 1, half = t & 1;
        int p = p0 + lp;
        int cnt = d_count[b];
        int kb = half * 32;
        if (p < cnt && p < dim) {
            int q = d_order[b * DIMMAX + p];
            int i1 = q / Nn, i2 = q - i1 * Nn;
            const float4* Ga = (const float4*)(d_A + ((size_t)(b * Nn + i1)) * 64 + kb);
            const float4* Cc = (const float4*)(d_C + ((size_t)(b * Nn + i2)) * 64 + kb);
#pragma unroll
            for (int kk = 0; kk < 8; ++kk) {
                float4 a = Ga[kk], c = Cc[kk];
                int k = kb + 4 * kk;
                sm->X[xaddr(k + 0, lp)] = my_tanh(sm->Gg[k + 0] + a.x + c.x);
                sm->X[xaddr(k + 1, lp)] = my_tanh(sm->Gg[k + 1] + a.y + c.y);
                sm->X[xaddr(k + 2, lp)] = my_tanh(sm->Gg[k + 2] + a.z + c.z);
                sm->X[xaddr(k + 3, lp)] = my_tanh(sm->Gg[k + 3] + a.w + c.w);
            }
        } else {
            // invalid / out-of-range: zeroed input -> pre-activation = b0
#pragma unroll
            for (int k = kb; k < kb + 32; ++k) sm->X[xaddr(k, lp)] = my_tanh(sm->b0[k]);
        }
    }
    __syncthreads();

    int jg = t & 7, pg = t >> 3;
    float acc[8][4];

    // ---- layer 1 ----
    gemm64s(sm->X, sm->Wa1, sm->Wb1, sm->b1, acc, jg, pg);
    __syncthreads();
    tanh_store(sm->X, acc, jg, pg);
    __syncthreads();

    // ---- layer 2 ----
    gemm64s(sm->X, sm->Wa2, sm->Wb2, sm->b2, acc, jg, pg);
    __syncthreads();
    tanh_store(sm->X, acc, jg, pg);
    __syncthreads();

    // ---- layer 3: 2 threads per pair, shfl-combined (64 -> 2) ----
    {
        int lp = t >> 1, half = t & 1;
        int p = p0 + lp;
        float lg = 0.f, bl = 0.f;
        int kb = half * 32;
#pragma unroll
        for (int kk = 0; kk < 32; ++kk) {
            int k = kb + kk;
            float h = sm->X[xaddr(k, lp)];
            lg += h * sm->W3[2 * k + 0];
            bl += h * sm->W3[2 * k + 1];
        }
        lg += __shfl_xor_sync(0xffffffffu, lg, 1);
        bl += __shfl_xor_sync(0xffffffffu, bl, 1);
        if (half == 0 && p < dim) {
            // e = exp(logit - (b3 + SA)); softmax is shift-invariant
            d_logit[b * DIMMAX + p] = __expf(lg - SA);
            d_sig[b * DIMMAX + p] = 1.0f / (1.0f + __expf(-(bl + sm->b3[1])));
        }
    }
}

// ---------------- kernel 3: sum(e) + scatter (one block per batch) -------------
__global__ void softscatter_kernel(float* __restrict__ out, const int* __restrict__ dimp) {
    int b = blockIdx.x, t = threadIdx.x;  // 1024 threads
    int dim = read_dim(dimp);
    __shared__ float red[32];
    __shared__ float sInv;
    float* ob = out + (size_t)b * 20000;
    float s = 0.f;
    for (int p = t; p < dim; p += 1024) s += d_logit[b * DIMMAX + p];
#pragma unroll
    for (int o = 16; o; o >>= 1) s += __shfl_xor_sync(0xffffffffu, s, o);
    if ((t & 31) == 0) red[t >> 5] = s;
    __syncthreads();
    if (t == 0) {
        float tot = 0.f;
        for (int i = 0; i < 32; ++i) tot += red[i];
        sInv = 1.0f / tot;
    }
    __syncthreads();
    float inv = sInv;
    int cnt = d_count[b];
    int lim = (cnt < dim) ? cnt : dim;
    for (int p = t; p < lim; p += 1024) {
        int q = d_order[b * DIMMAX + p];
        float pi = d_logit[b * DIMMAX + p] * inv;
        float sg = d_sig[b * DIMMAX + p];
        ob[q] = pi * sg;
        ob[10000 + q] = pi * (1.0f - sg);
    }
}

// ---------------- launcher (3 launches, single stream) ----------------
extern "C" void kernel_launch(void* const* d_in, const int* in_sizes, int n_in,
                              void* d_out, int out_size) {
    const float* emb = (const float*)d_in[0];
    const int* dimp;
    int base;
    if (n_in >= 18 && in_sizes[1] == 1) {   // dict order: emb, dim, actor..., critic...
        dimp = (const int*)d_in[1];
        base = 2;
    } else {                                // signature order: emb, actor..., critic..., dim
        dimp = (const int*)d_in[n_in - 1];
        base = 1;
    }
    const float* aw0 = (const float*)d_in[base + 0];
    const float* ab0 = (const float*)d_in[base + 1];
    const float* aw1 = (const float*)d_in[base + 2];
    const float* ab1 = (const float*)d_in[base + 3];
    const float* aw2 = (const float*)d_in[base + 4];
    const float* ab2 = (const float*)d_in[base + 5];
    const float* aw3 = (const float*)d_in[base + 6];
    const float* ab3 = (const float*)d_in[base + 7];
    const float* cw0 = (const float*)d_in[base + 8];
    const float* cb0 = (const float*)d_in[base + 9];
    const float* cw1 = (const float*)d_in[base + 10];
    const float* cb1 = (const float*)d_in[base + 11];
    const float* cw2 = (const float*)d_in[base + 12];
    const float* cb2 = (const float*)d_in[base + 13];
    const float* cw3 = (const float*)d_in[base + 14];
    const float* cb3 = (const float*)d_in[base + 15];

    float* out = (float*)d_out;
    int voff = out_size - Bz;  // value slot after the filled region (expect 640000)

    static int init_done = 0;
    if (!init_done) {
        cudaFuncSetAttribute(pair_kernel, cudaFuncAttributeMaxDynamicSharedMemorySize,
                             PAIR_SMEM_BYTES);
        cudaFuncSetAttribute(prep_kernel, cudaFuncAttributeMaxDynamicSharedMemorySize,
                             PREP_SMEM);
        init_done = 1;
    }

    prep_kernel<<<dim3(Bz, 13), 256, PREP_SMEM>>>(emb, aw0, ab0, cw0, cb0, cw1, cb1,
                                                  cw2, cb2, cw3, cb3, out, voff, dimp);
    pair_kernel<<<dim3(PBLK, Bz), 256, PAIR_SMEM_BYTES>>>(aw1, ab1, aw2, ab2, aw3, ab3,
                                                          ab0, dimp);
    softscatter_kernel<<<Bz, 1024>>>(out, dimp);
}

// round 8
// speedup vs baseline: 1.1750x; 1.1253x over previous
#include <cuda_runtime.h>
#include <cstdint>
#include <math.h>

#define Bz     32
#define Nn     100
#define Ff     514
#define FE     614      // 514 feats + 100 mask cols
#define ROWSE  101
#define NN2    10000
#define DIMMAX 10000
#define BLKP   128      // pairs per block in pair kernel
#define PBLK   79       // ceil(DIMMAX/128)

// ---------------- scratch (static device globals; no allocation) ----------------
__device__ int   d_order[Bz * DIMMAX];
__device__ int   d_count[Bz];
__device__ float d_Gg[Bz * 64];
__device__ float d_A[Bz * Nn * 64];
__device__ float d_C[Bz * Nn * 64];
__device__ float d_logit[Bz * DIMMAX];   // holds e = exp(logit - shift)
__device__ float d_sig[Bz * DIMMAX];

// ---------------- small helpers ----------------
__device__ __forceinline__ int read_dim(const int* p) {
    int v = *p;
    if (v < 1 || v > DIMMAX) {            // safety: tolerate float-encoded scalar
        float f = __int_as_float(v);
        v = (int)f;
    }
    if (v < 0) v = 0;
    if (v > DIMMAX) v = DIMMAX;
    return v;
}

__device__ __forceinline__ float my_tanh(float x) {
    // tanh(x) = 1 - 2/(exp(2x)+1)   (exact identity; __expf rel err ~2^-22)
    float e = __expf(2.0f * x);
    return 1.0f - __fdividef(2.0f, e + 1.0f);
}

__device__ __forceinline__ unsigned f2tf(float x) {
    unsigned r;
    asm("cvt.rna.tf32.f32 %0, %1;" : "=r"(r) : "f"(x));
    return r;
}

__device__ __forceinline__ void mma_tf32(float (&d)[4], const unsigned (&a)[4],
                                         const unsigned (&b)[2]) {
    asm volatile(
        "mma.sync.aligned.m16n8k8.row.col.f32.tf32.tf32.f32 "
        "{%0,%1,%2,%3}, {%4,%5,%6,%7}, {%8,%9}, {%0,%1,%2,%3};"
        : "+f"(d[0]), "+f"(d[1]), "+f"(d[2]), "+f"(d[3])
        : "r"(a[0]), "r"(a[1]), "r"(a[2]), "r"(a[3]), "r"(b[0]), "r"(b[1]));
}

// ================= prep kernel: scan / head / ac(10) / zero via blockIdx.y ======
// dynamic smem: 10x516 rows (20640B) + 2x 32x128 W chunks (32768B) = 53408B
#define PREP_SMEM (20640 + 32768)

__device__ void scan_role(const float* __restrict__ emb, int b, int dim, char* sh) {
    int t = threadIdx.x;           // 256
    int lane = t & 31, w = t >> 5; // 8 warps
    unsigned* bal = (unsigned*)sh;         // [320]
    int* pre = (int*)(sh + 320 * 4);       // [320]
#pragma unroll
    for (int c = 0; c < 40; ++c) {
        int idx = c * 256 + t;
        int flag = 0;
        if (idx < NN2) {
            int i = idx / Nn, j = idx - i * Nn;
            flag = emb[(size_t)(b * ROWSE + 1 + i) * FE + Ff + j] > 0.5f;
        }
        unsigned bl = __ballot_sync(0xffffffffu, flag);
        if (lane == 0) bal[c * 8 + w] = bl;
    }
    __syncthreads();
    if (t < 32) {
        int loc[10];
        int s = 0;
#pragma unroll
        for (int k = 0; k < 10; ++k) {
            int v = __popc(bal[lane * 10 + k]);
            loc[k] = s;
            s += v;
        }
        int p = s;
#pragma unroll
        for (int o = 1; o < 32; o <<= 1) {
            int n = __shfl_up_sync(0xffffffffu, p, o);
            if (lane >= o) p += n;
        }
        int off = p - s;
#pragma unroll
        for (int k = 0; k < 10; ++k) pre[lane * 10 + k] = off + loc[k];
        if (lane == 31) d_count[b] = p;
    }
    __syncthreads();
#pragma unroll
    for (int c = 0; c < 40; ++c) {
        unsigned bl = bal[c * 8 + w];
        if ((bl >> lane) & 1u) {
            int rank = pre[c * 8 + w] + __popc(bl & ((1u << lane) - 1u));
            if (rank < dim) d_order[b * DIMMAX + rank] = c * 256 + t;
        }
    }
}

__device__ void head_role(const float* __restrict__ emb,
                          const float* __restrict__ aw0, const float* __restrict__ ab0,
                          const float* __restrict__ cw0, const float* __restrict__ cb0,
                          const float* __restrict__ cw1, const float* __restrict__ cb1,
                          const float* __restrict__ cw2, const float* __restrict__ cb2,
                          const float* __restrict__ cw3, const float* __restrict__ cb3,
                          float* __restrict__ out, int voff, int b, char* sh) {
    float* row = (float*)sh;              // [516]
    float* part = row + 516;              // [256]
    float* ha = part + 256;               // [64]
    float* hb = ha + 64;                  // [64]
    int t = threadIdx.x;                  // 256
    for (int k = t; k < Ff; k += 256) row[k] = emb[(size_t)b * ROWSE * FE + k];
    __syncthreads();
    int j = t & 63, ks = t >> 6;  // 4-way k split
    {
        float acc = 0.f;
        for (int k = ks; k < Ff; k += 4) acc += row[k] * aw0[(size_t)k * 64 + j];
        part[t] = acc;
    }
    __syncthreads();
    if (t < 64) {
        float s = ab0[j] + part[j] + part[64 + j] + part[128 + j] + part[192 + j];
        d_Gg[b * 64 + j] = s;
    }
    __syncthreads();
    {
        float acc = 0.f;
        for (int k = ks; k < Ff; k += 4) acc += row[k] * cw0[(size_t)k * 64 + j];
        part[t] = acc;
    }
    __syncthreads();
    if (t < 64) {
        float s = cb0[j] + part[j] + part[64 + j] + part[128 + j] + part[192 + j];
        ha[j] = my_tanh(s);
    }
    __syncthreads();
    if (t < 64) {
        float acc = cb1[t];
        for (int k = 0; k < 64; ++k) acc += ha[k] * cw1[k * 64 + t];
        hb[t] = my_tanh(acc);
    }
    __syncthreads();
    if (t < 64) {
        float acc = cb2[t];
        for (int k = 0; k < 64; ++k) acc += hb[k] * cw2[k * 64 + t];
        ha[t] = my_tanh(acc);
    }
    __syncthreads();
    if (t == 0) {
        float v = cb3[0];
        for (int k = 0; k < 64; ++k) v += ha[k] * cw3[k];
        out[voff + b] = v;
    }
}

// A = nodes @ W0[514:1028], C = nodes @ W0[1028:1542]
// 10-node group per block; double-buffered W staging, hoisted addressing.
__device__ void ac_role(const float* __restrict__ emb, const float* __restrict__ w0,
                        int b, int gy, char* sh) {
    float (*rows)[516] = (float (*)[516])sh;          // 10 x 516
    float* sW = (float*)(sh + 20640);                 // 2 x 4096 floats
    int t = threadIdx.x;          // 256
    int R0 = 1 + gy * 10;
    for (int e = t; e < 10 * Ff; e += 256) {
        int r = e / Ff, k = e - r * Ff;
        rows[r][k] = emb[(size_t)(b * ROWSE + R0 + r) * FE + k];
    }
    int jj = t & 127, half = t >> 7;
    const float* wA = w0 + (size_t)Ff * 64;           // A weights [514][64]
    const float* wC = wA + (size_t)Ff * 64;           // C weights [514][64]
    // column pointer for this thread's staging lane (jj const, k = half + 2i + 32*kc)
    const float* wptr = ((jj < 64) ? (wA + jj) : (wC + (jj - 64))) + half * 64;

    float reg[16];
#pragma unroll
    for (int i = 0; i < 16; ++i) reg[i] = wptr[i * 128];
    wptr += 2048;
#pragma unroll
    for (int i = 0; i < 16; ++i) sW[t + 256 * i] = reg[i];
    __syncthreads();

    float acc[5];
#pragma unroll
    for (int rr = 0; rr < 5; ++rr) acc[rr] = 0.f;

    int j = jj;
    for (int kc = 0; kc < 16; ++kc) {
        const float* cur = sW + (kc & 1) * 4096;
        float* alt = sW + ((kc & 1) ^ 1) * 4096;
        if (kc < 15) {
#pragma unroll
            for (int i = 0; i < 16; ++i) reg[i] = wptr[i * 128];
            wptr += 2048;
        }
        int kb = kc * 32;
#pragma unroll
        for (int kk = 0; kk < 32; kk += 4) {
            float wv0 = cur[(kk + 0) * 128 + j];
            float wv1 = cur[(kk + 1) * 128 + j];
            float wv2 = cur[(kk + 2) * 128 + j];
            float wv3 = cur[(kk + 3) * 128 + j];
#pragma unroll
            for (int rr = 0; rr < 5; ++rr) {
                int r = half + 2 * rr;
                float4 hv = *(const float4*)&rows[r][kb + kk];
                acc[rr] += hv.x * wv0 + hv.y * wv1 + hv.z * wv2 + hv.w * wv3;
            }
        }
        if (kc < 15) {
#pragma unroll
            for (int i = 0; i < 16; ++i) alt[t + 256 * i] = reg[i];
        }
        __syncthreads();
    }
    // tail k = 512, 513
    {
        const float* wcol = (j < 64) ? (wA + j) : (wC + (j - 64));
        float wv0 = wcol[(size_t)512 * 64], wv1 = wcol[(size_t)513 * 64];
#pragma unroll
        for (int rr = 0; rr < 5; ++rr) {
            int r = half + 2 * rr;
            acc[rr] += rows[r][512] * wv0 + rows[r][513] * wv1;
        }
    }
#pragma unroll
    for (int rr = 0; rr < 5; ++rr) {
        int node = gy * 10 + half + 2 * rr;
        if (j < 64) d_A[((size_t)(b * Nn + node)) * 64 + j] = acc[rr];
        else        d_C[((size_t)(b * Nn + node)) * 64 + (j - 64)] = acc[rr];
    }
}

__device__ void zero_role(float* __restrict__ out, int b) {
    float4 z = make_float4(0.f, 0.f, 0.f, 0.f);
    float4* ob = (float4*)(out + (size_t)b * 20000);
    for (int i = threadIdx.x; i < 5000; i += 256) ob[i] = z;
}

__global__ void prep_kernel(const float* __restrict__ emb,
                            const float* __restrict__ aw0, const float* __restrict__ ab0,
                            const float* __restrict__ cw0, const float* __restrict__ cb0,
                            const float* __restrict__ cw1, const float* __restrict__ cb1,
                            const float* __restrict__ cw2, const float* __restrict__ cb2,
                            const float* __restrict__ cw3, const float* __restrict__ cb3,
                            float* __restrict__ out, int voff,
                            const int* __restrict__ dimp) {
    extern __shared__ __align__(16) char sh[];
    int b = blockIdx.x;
    int role = blockIdx.y;
    if (role < 10) {
        ac_role(emb, aw0, b, role, sh);
    } else if (role == 10) {
        scan_role(emb, b, read_dim(dimp), sh);
    } else if (role == 11) {
        head_role(emb, aw0, ab0, cw0, cb0, cw1, cb1, cw2, cb2, cw3, cb3, out, voff, b, sh);
    } else {
        zero_role(out, b);
    }
}

// ============== pair kernel v6: tf32 tensor-core MMA (3xTF32, fp32-accurate) ====
// Per block: 128 pairs. 8 warps, each owns one 16-row m-strip through both layers.
// X: fp32 [128][68] (pad-68 => conflict-free fragment access).
// W: hi/lo tf32 split, col-major [n][68].
struct PairSmem {
    unsigned Wh1[64 * 68], Wl1[64 * 68];
    unsigned Wh2[64 * 68], Wl2[64 * 68];
    float X[128 * 68];
    float W3[128];                // [k][2]
    float b1[64], b2[64], b0[64], Gg[64];
    float b3[2];
};
#define PAIR_SMEM_BYTES ((int)sizeof(PairSmem))

__device__ __forceinline__ void mma_layer(float* __restrict__ X,
                                          const unsigned* __restrict__ Wh,
                                          const unsigned* __restrict__ Wl,
                                          const float* __restrict__ bias,
                                          int w, int lane) {
    int r = lane >> 2, c = lane & 3;
    float acc[8][4];
#pragma unroll
    for (int nt = 0; nt < 8; ++nt) {
        float bv0 = bias[nt * 8 + 2 * c], bv1 = bias[nt * 8 + 2 * c + 1];
        acc[nt][0] = bv0; acc[nt][1] = bv1; acc[nt][2] = bv0; acc[nt][3] = bv1;
    }
    const float* Xa = X + (w * 16 + r) * 68;
    const float* Xb = Xa + 8 * 68;
#pragma unroll
    for (int k8 = 0; k8 < 8; ++k8) {
        float x0 = Xa[k8 * 8 + c];
        float x1 = Xb[k8 * 8 + c];
        float x2 = Xa[k8 * 8 + c + 4];
        float x3 = Xb[k8 * 8 + c + 4];
        unsigned ah[4], al[4];
        ah[0] = f2tf(x0); al[0] = f2tf(x0 - __uint_as_float(ah[0]));
        ah[1] = f2tf(x1); al[1] = f2tf(x1 - __uint_as_float(ah[1]));
        ah[2] = f2tf(x2); al[2] = f2tf(x2 - __uint_as_float(ah[2]));
        ah[3] = f2tf(x3); al[3] = f2tf(x3 - __uint_as_float(ah[3]));
#pragma unroll
        for (int nt = 0; nt < 8; ++nt) {
            const unsigned* wp = Wh + (nt * 8 + r) * 68 + k8 * 8 + c;
            const unsigned* wq = Wl + (nt * 8 + r) * 68 + k8 * 8 + c;
            unsigned bh[2] = {wp[0], wp[4]};
            unsigned bl2[2] = {wq[0], wq[4]};
            mma_tf32(acc[nt], ah, bh);   // x_hi * w_hi
            mma_tf32(acc[nt], al, bh);   // x_lo * w_hi
            mma_tf32(acc[nt], ah, bl2);  // x_hi * w_lo
        }
    }
    __syncwarp();   // all lanes done reading X (own strip only) before overwrite
    float* Xo = X + (w * 16 + r) * 68;
    float* Xo8 = Xo + 8 * 68;
#pragma unroll
    for (int nt = 0; nt < 8; ++nt) {
        int cb = nt * 8 + 2 * c;
        Xo[cb] = my_tanh(acc[nt][0]);
        Xo[cb + 1] = my_tanh(acc[nt][1]);
        Xo8[cb] = my_tanh(acc[nt][2]);
        Xo8[cb + 1] = my_tanh(acc[nt][3]);
    }
    __syncwarp();
}

__global__ __launch_bounds__(256, 2) void pair_kernel(
    const float* __restrict__ aw1, const float* __restrict__ ab1,
    const float* __restrict__ aw2, const float* __restrict__ ab2,
    const float* __restrict__ aw3, const float* __restrict__ ab3,
    const float* __restrict__ ab0, const int* __restrict__ dimp) {
    extern __shared__ __align__(16) char smem_raw[];
    PairSmem* sm = (PairSmem*)smem_raw;
    int dim = read_dim(dimp);
    int p0 = blockIdx.x * BLKP;
    if (p0 >= dim) return;               // uniform block exit
    int b = blockIdx.y, t = threadIdx.x;

    // ---- stage weights (tf32 hi/lo split, transposed to [n][68]) + biases ----
#pragma unroll
    for (int i = 0; i < 16; ++i) {
        int e = t + 256 * i;
        int k = e >> 6, n = e & 63;
        int di = n * 68 + k;
        float w1 = aw1[e], w2 = aw2[e];
        unsigned h1 = f2tf(w1);
        sm->Wh1[di] = h1;
        sm->Wl1[di] = f2tf(w1 - __uint_as_float(h1));
        unsigned h2 = f2tf(w2);
        sm->Wh2[di] = h2;
        sm->Wl2[di] = f2tf(w2 - __uint_as_float(h2));
    }
    if (t < 64) {
        sm->b1[t] = ab1[t];
        sm->b2[t] = ab2[t];
        sm->b0[t] = ab0[t];
        sm->Gg[t] = d_Gg[b * 64 + t];
        sm->W3[2 * t + 0] = aw3[2 * t + 0];
        sm->W3[2 * t + 1] = aw3[2 * t + 1];
    }
    if (t < 2) sm->b3[t] = ab3[t];
    __syncthreads();

    // shift SA = sum_k |W3[k][0]|  (logit part <= SA since |h| < 1)
    float SA = 0.f;
#pragma unroll
    for (int k = 0; k < 64; ++k) SA += fabsf(sm->W3[2 * k]);

    // ---- layer 0: 2 threads per pair, each builds 32 features (row-major X) ----
    {
        int lp = t >> 1, half = t & 1;
        int p = p0 + lp;
        int cnt = d_count[b];
        int kb = half * 32;
        float* xr = sm->X + lp * 68 + kb;
        if (p < cnt && p < dim) {
            int q = d_order[b * DIMMAX + p];
            int i1 = q / Nn, i2 = q - i1 * Nn;
            const float4* Ga = (const float4*)(d_A + ((size_t)(b * Nn + i1)) * 64 + kb);
            const float4* Cc = (const float4*)(d_C + ((size_t)(b * Nn + i2)) * 64 + kb);
#pragma unroll
            for (int kk = 0; kk < 8; ++kk) {
                float4 a = Ga[kk], c = Cc[kk];
                int k = kb + 4 * kk;
                float4 v;
                v.x = my_tanh(sm->Gg[k + 0] + a.x + c.x);
                v.y = my_tanh(sm->Gg[k + 1] + a.y + c.y);
                v.z = my_tanh(sm->Gg[k + 2] + a.z + c.z);
                v.w = my_tanh(sm->Gg[k + 3] + a.w + c.w);
                *(float4*)(xr + 4 * kk) = v;
            }
        } else {
            // invalid / out-of-range: zeroed input -> pre-activation = b0
#pragma unroll
            for (int kk = 0; kk < 32; ++kk) xr[kk] = my_tanh(sm->b0[kb + kk]);
        }
    }
    __syncwarp();   // writer rows == this warp's m-strip; warp-local handoff

    int w = t >> 5, lane = t & 31;
    mma_layer(sm->X, sm->Wh1, sm->Wl1, sm->b1, w, lane);
    mma_layer(sm->X, sm->Wh2, sm->Wl2, sm->b2, w, lane);

    // ---- layer 3: 2 threads per pair, shfl-combined (64 -> 2) ----
    {
        int lp = t >> 1, half = t & 1;
        int p = p0 + lp;
        const float* xr = sm->X + lp * 68 + half * 32;
        float lg = 0.f, bl = 0.f;
        int kb = half * 32;
#pragma unroll
        for (int kk = 0; kk < 32; ++kk) {
            float h = xr[kk];
            lg += h * sm->W3[2 * (kb + kk) + 0];
            bl += h * sm->W3[2 * (kb + kk) + 1];
        }
        lg += __shfl_xor_sync(0xffffffffu, lg, 1);
        bl += __shfl_xor_sync(0xffffffffu, bl, 1);
        if (half == 0 && p < dim) {
            // e = exp(logit - (b3 + SA)); softmax is shift-invariant
            d_logit[b * DIMMAX + p] = __expf(lg - SA);
            d_sig[b * DIMMAX + p] = 1.0f / (1.0f + __expf(-(bl + sm->b3[1])));
        }
    }
}

// ---------------- kernel 3: sum(e) + scatter (one block per batch) -------------
__global__ void softscatter_kernel(float* __restrict__ out, const int* __restrict__ dimp) {
    int b = blockIdx.x, t = threadIdx.x;  // 1024 threads
    int dim = read_dim(dimp);
    __shared__ float red[32];
    __shared__ float sInv;
    float* ob = out + (size_t)b * 20000;
    float s = 0.f;
    for (int p = t; p < dim; p += 1024) s += d_logit[b * DIMMAX + p];
#pragma unroll
    for (int o = 16; o; o >>= 1) s += __shfl_xor_sync(0xffffffffu, s, o);
    if ((t & 31) == 0) red[t >> 5] = s;
    __syncthreads();
    if (t == 0) {
        float tot = 0.f;
        for (int i = 0; i < 32; ++i) tot += red[i];
        sInv = 1.0f / tot;
    }
    __syncthreads();
    float inv = sInv;
    int cnt = d_count[b];
    int lim = (cnt < dim) ? cnt : dim;
    for (int p = t; p < lim; p += 1024) {
        int q = d_order[b * DIMMAX + p];
        float pi = d_logit[b * DIMMAX + p] * inv;
        float sg = d_sig[b * DIMMAX + p];
        ob[q] = pi * sg;
        ob[10000 + q] = pi * (1.0f - sg);
    }
}

// ---------------- launcher (3 launches, single stream) ----------------
extern "C" void kernel_launch(void* const* d_in, const int* in_sizes, int n_in,
                              void* d_out, int out_size) {
    const float* emb = (const float*)d_in[0];
    const int* dimp;
    int base;
    if (n_in >= 18 && in_sizes[1] == 1) {   // dict order: emb, dim, actor..., critic...
        dimp = (const int*)d_in[1];
        base = 2;
    } else {                                // signature order: emb, actor..., critic..., dim
        dimp = (const int*)d_in[n_in - 1];
        base = 1;
    }
    const float* aw0 = (const float*)d_in[base + 0];
    const float* ab0 = (const float*)d_in[base + 1];
    const float* aw1 = (const float*)d_in[base + 2];
    const float* ab1 = (const float*)d_in[base + 3];
    const float* aw2 = (const float*)d_in[base + 4];
    const float* ab2 = (const float*)d_in[base + 5];
    const float* aw3 = (const float*)d_in[base + 6];
    const float* ab3 = (const float*)d_in[base + 7];
    const float* cw0 = (const float*)d_in[base + 8];
    const float* cb0 = (const float*)d_in[base + 9];
    const float* cw1 = (const float*)d_in[base + 10];
    const float* cb1 = (const float*)d_in[base + 11];
    const float* cw2 = (const float*)d_in[base + 12];
    const float* cb2 = (const float*)d_in[base + 13];
    const float* cw3 = (const float*)d_in[base + 14];
    const float* cb3 = (const float*)d_in[base + 15];

    float* out = (float*)d_out;
    int voff = out_size - Bz;  // value slot after the filled region (expect 640000)

    static int init_done = 0;
    if (!init_done) {
        cudaFuncSetAttribute(pair_kernel, cudaFuncAttributeMaxDynamicSharedMemorySize,
                             PAIR_SMEM_BYTES);
        cudaFuncSetAttribute(prep_kernel, cudaFuncAttributeMaxDynamicSharedMemorySize,
                             PREP_SMEM);
        init_done = 1;
    }

    prep_kernel<<<dim3(Bz, 13), 256, PREP_SMEM>>>(emb, aw0, ab0, cw0, cb0, cw1, cb1,
                                                  cw2, cb2, cw3, cb3, out, voff, dimp);
    pair_kernel<<<dim3(PBLK, Bz), 256, PAIR_SMEM_BYTES>>>(aw1, ab1, aw2, ab2, aw3, ab3,
                                                          ab0, dimp);
    softscatter_kernel<<<Bz, 1024>>>(out, dimp);
}

// round 9
// speedup vs baseline: 1.2308x; 1.0475x over previous
#include <cuda_runtime.h>
#include <cuda_bf16.h>
#include <cstdint>
#include <math.h>

#define Bz     32
#define Nn     100
#define Ff     514
#define FE     614      // 514 feats + 100 mask cols
#define ROWSE  101
#define NN2    10000
#define DIMMAX 10000
#define BLKP   128      // pairs per block in pair kernel
#define PBLK   79       // ceil(DIMMAX/128)
#define XPAD   36

// ---------------- scratch (static device globals; no allocation) ----------------
__device__ int   d_order[Bz * DIMMAX];
__device__ int   d_count[Bz];
__device__ float d_Gg[Bz * 64];
__device__ float d_A[Bz * Nn * 64];
__device__ float d_C[Bz * Nn * 64];
__device__ float d_logit[Bz * DIMMAX];   // holds e = exp(logit - shift)
__device__ float d_sig[Bz * DIMMAX];
__device__ float d_esum[Bz];

// ---------------- small helpers ----------------
__device__ __forceinline__ int read_dim(const int* p) {
    int v = *p;
    if (v < 1 || v > DIMMAX) {            // safety: tolerate float-encoded scalar
        float f = __int_as_float(v);
        v = (int)f;
    }
    if (v < 0) v = 0;
    if (v > DIMMAX) v = DIMMAX;
    return v;
}

__device__ __forceinline__ float my_tanh(float x) {
    // tanh(x) = 1 - 2/(exp(2x)+1)   (exact identity; __expf rel err ~2^-22)
    float e = __expf(2.0f * x);
    return 1.0f - __fdividef(2.0f, e + 1.0f);
}

__device__ __forceinline__ unsigned pack_bf(__nv_bfloat16 a, __nv_bfloat16 b) {
    __nv_bfloat162 v;
    v.x = a;  // low half
    v.y = b;  // high half
    return *reinterpret_cast<unsigned*>(&v);
}

__device__ __forceinline__ void mma_bf16(float (&d)[4], const unsigned (&a)[4],
                                         const unsigned (&b)[2]) {
    asm volatile(
        "mma.sync.aligned.m16n8k16.row.col.f32.bf16.bf16.f32 "
        "{%0,%1,%2,%3}, {%4,%5,%6,%7}, {%8,%9}, {%0,%1,%2,%3};"
        : "+f"(d[0]), "+f"(d[1]), "+f"(d[2]), "+f"(d[3])
        : "r"(a[0]), "r"(a[1]), "r"(a[2]), "r"(a[3]), "r"(b[0]), "r"(b[1]));
}

// ================= prep kernel: ac(20) / scan / head / zero via blockIdx.y ======
// dynamic smem: 5x516 rows (10320B) + 2x 32x128 W chunks (32768B) = 43088B
#define PREP_SMEM (10320 + 32768)

__device__ void scan_role(const float* __restrict__ emb, int b, int dim, char* sh) {
    int t = threadIdx.x;           // 256
    int lane = t & 31, w = t >> 5; // 8 warps
    unsigned* bal = (unsigned*)sh;         // [320]
    int* pre = (int*)(sh + 320 * 4);       // [320]
#pragma unroll
    for (int c = 0; c < 40; ++c) {
        int idx = c * 256 + t;
        int flag = 0;
        if (idx < NN2) {
            int i = idx / Nn, j = idx - i * Nn;
            flag = emb[(size_t)(b * ROWSE + 1 + i) * FE + Ff + j] > 0.5f;
        }
        unsigned bl = __ballot_sync(0xffffffffu, flag);
        if (lane == 0) bal[c * 8 + w] = bl;
    }
    __syncthreads();
    if (t < 32) {
        int loc[10];
        int s = 0;
#pragma unroll
        for (int k = 0; k < 10; ++k) {
            int v = __popc(bal[lane * 10 + k]);
            loc[k] = s;
            s += v;
        }
        int p = s;
#pragma unroll
        for (int o = 1; o < 32; o <<= 1) {
            int n = __shfl_up_sync(0xffffffffu, p, o);
            if (lane >= o) p += n;
        }
        int off = p - s;
#pragma unroll
        for (int k = 0; k < 10; ++k) pre[lane * 10 + k] = off + loc[k];
        if (lane == 31) d_count[b] = p;
    }
    __syncthreads();
#pragma unroll
    for (int c = 0; c < 40; ++c) {
        unsigned bl = bal[c * 8 + w];
        if ((bl >> lane) & 1u) {
            int rank = pre[c * 8 + w] + __popc(bl & ((1u << lane) - 1u));
            if (rank < dim) d_order[b * DIMMAX + rank] = c * 256 + t;
        }
    }
}

__device__ void head_role(const float* __restrict__ emb,
                          const float* __restrict__ aw0, const float* __restrict__ ab0,
                          const float* __restrict__ cw0, const float* __restrict__ cb0,
                          const float* __restrict__ cw1, const float* __restrict__ cb1,
                          const float* __restrict__ cw2, const float* __restrict__ cb2,
                          const float* __restrict__ cw3, const float* __restrict__ cb3,
                          float* __restrict__ out, int voff, int b, char* sh) {
    float* row = (float*)sh;              // [516]
    float* part = row + 516;              // [256]
    float* ha = part + 256;               // [64]
    float* hb = ha + 64;                  // [64]
    int t = threadIdx.x;                  // 256
    for (int k = t; k < Ff; k += 256) row[k] = emb[(size_t)b * ROWSE * FE + k];
    __syncthreads();
    int j = t & 63, ks = t >> 6;  // 4-way k split
    {
        float acc = 0.f;
        for (int k = ks; k < Ff; k += 4) acc += row[k] * aw0[(size_t)k * 64 + j];
        part[t] = acc;
    }
    __syncthreads();
    if (t < 64) {
        float s = ab0[j] + part[j] + part[64 + j] + part[128 + j] + part[192 + j];
        d_Gg[b * 64 + j] = s;
    }
    __syncthreads();
    {
        float acc = 0.f;
        for (int k = ks; k < Ff; k += 4) acc += row[k] * cw0[(size_t)k * 64 + j];
        part[t] = acc;
    }
    __syncthreads();
    if (t < 64) {
        float s = cb0[j] + part[j] + part[64 + j] + part[128 + j] + part[192 + j];
        ha[j] = my_tanh(s);
    }
    __syncthreads();
    if (t < 64) {
        float acc = cb1[t];
        for (int k = 0; k < 64; ++k) acc += ha[k] * cw1[k * 64 + t];
        hb[t] = my_tanh(acc);
    }
    __syncthreads();
    if (t < 64) {
        float acc = cb2[t];
        for (int k = 0; k < 64; ++k) acc += hb[k] * cw2[k * 64 + t];
        ha[t] = my_tanh(acc);
    }
    __syncthreads();
    if (t == 0) {
        float v = cb3[0];
        for (int k = 0; k < 64; ++k) v += ha[k] * cw3[k];
        out[voff + b] = v;
    }
}

template <int NR>
__device__ __forceinline__ void ac_inner(const float* __restrict__ cur,
                                         float (&acc)[3],
                                         const float (*rows)[516],
                                         int rbase, int kb, int j) {
#pragma unroll
    for (int kk = 0; kk < 32; kk += 4) {
        float wv0 = cur[(kk + 0) * 128 + j];
        float wv1 = cur[(kk + 1) * 128 + j];
        float wv2 = cur[(kk + 2) * 128 + j];
        float wv3 = cur[(kk + 3) * 128 + j];
#pragma unroll
        for (int rr = 0; rr < NR; ++rr) {
            float4 hv = *(const float4*)&rows[rbase + rr][kb + kk];
            acc[rr] += hv.x * wv0 + hv.y * wv1 + hv.z * wv2 + hv.w * wv3;
        }
    }
}

// A = nodes @ W0[514:1028], C = nodes @ W0[1028:1542]
// 5-node group per block; double-buffered float4 W staging.
__device__ void ac_role(const float* __restrict__ emb, const float* __restrict__ w0,
                        int b, int gy, char* sh) {
    float (*rows)[516] = (float (*)[516])sh;          // 5 x 516
    float* sW = (float*)(sh + 10320);                 // 2 x 4096 floats
    int t = threadIdx.x;          // 256
    int R0 = 1 + gy * 5;
    for (int e = t; e < 5 * Ff; e += 256) {
        int r = e / Ff, k = e - r * Ff;
        rows[r][k] = emb[(size_t)(b * ROWSE + R0 + r) * FE + k];
    }
    int j = t & 127, half = t >> 7;
    const float* wA = w0 + (size_t)Ff * 64;           // A weights [514][64]
    const float* wC = wA + (size_t)Ff * 64;           // C weights [514][64]
    // float4 staging: w5 = word-in-row (0..31), krow = this thread's base k (0..7)
    int w5 = t & 31, krow = t >> 5;
    const float4* wsrc = ((w5 < 16) ? ((const float4*)wA + w5)
                                    : ((const float4*)wC + (w5 - 16))) +
                         (size_t)krow * 16;

    float4 rb[4];
#pragma unroll
    for (int i = 0; i < 4; ++i) rb[i] = wsrc[(size_t)(8 * i) * 16];
#pragma unroll
    for (int i = 0; i < 4; ++i) ((float4*)sW)[t + 256 * i] = rb[i];
    __syncthreads();

    float acc[3] = {0.f, 0.f, 0.f};
    int rbase = half * 3;   // half0: rows 0..2, half1: rows 3..4
    for (int kc = 0; kc < 16; ++kc) {
        const float* cur = sW + (kc & 1) * 4096;
        float* alt = sW + ((kc & 1) ^ 1) * 4096;
        if (kc < 15) {
#pragma unroll
            for (int i = 0; i < 4; ++i)
                rb[i] = wsrc[(size_t)((kc + 1) * 32 + 8 * i) * 16];
        }
        int kb = kc * 32;
        if (half == 0) ac_inner<3>(cur, acc, rows, 0, kb, j);
        else           ac_inner<2>(cur, acc, rows, 3, kb, j);
        if (kc < 15) {
#pragma unroll
            for (int i = 0; i < 4; ++i) ((float4*)alt)[t + 256 * i] = rb[i];
        }
        __syncthreads();
    }
    // tail k = 512, 513
    {
        const float* wcol = (j < 64) ? (wA + j) : (wC + (j - 64));
        float wv0 = wcol[(size_t)512 * 64], wv1 = wcol[(size_t)513 * 64];
        int nr = 3 - half;
        for (int rr = 0; rr < nr; ++rr) {
            acc[rr] += rows[rbase + rr][512] * wv0 + rows[rbase + rr][513] * wv1;
        }
    }
    int nr = 3 - half;
    for (int rr = 0; rr < nr; ++rr) {
        int node = gy * 5 + rbase + rr;
        if (j < 64) d_A[((size_t)(b * Nn + node)) * 64 + j] = acc[rr];
        else        d_C[((size_t)(b * Nn + node)) * 64 + (j - 64)] = acc[rr];
    }
}

__device__ void zero_role(float* __restrict__ out, int b) {
    float4 z = make_float4(0.f, 0.f, 0.f, 0.f);
    float4* ob = (float4*)(out + (size_t)b * 20000);
    for (int i = threadIdx.x; i < 5000; i += 256) ob[i] = z;
    if (threadIdx.x == 0) d_esum[b] = 0.f;
}

__global__ void prep_kernel(const float* __restrict__ emb,
                            const float* __restrict__ aw0, const float* __restrict__ ab0,
                            const float* __restrict__ cw0, const float* __restrict__ cb0,
                            const float* __restrict__ cw1, const float* __restrict__ cb1,
                            const float* __restrict__ cw2, const float* __restrict__ cb2,
                            const float* __restrict__ cw3, const float* __restrict__ cb3,
                            float* __restrict__ out, int voff,
                            const int* __restrict__ dimp) {
    extern __shared__ __align__(16) char sh[];
    int b = blockIdx.x;
    int role = blockIdx.y;
    if (role < 20) {
        ac_role(emb, aw0, b, role, sh);
    } else if (role == 20) {
        scan_role(emb, b, read_dim(dimp), sh);
    } else if (role == 21) {
        head_role(emb, aw0, ab0, cw0, cb0, cw1, cb1, cw2, cb2, cw3, cb3, out, voff, b, sh);
    } else {
        zero_role(out, b);
    }
}

// ============== pair kernel v7: bf16 m16n8k16 MMA, 3-term split =================
// 128 pairs/block, 8 warps; warp owns a 16-row m-strip through both layers.
// X, W stored as bf16x2 words (hi + lo arrays), XPAD=36 => conflict-free frags.
struct PairSmem {
    unsigned Wh1[64 * XPAD], Wl1[64 * XPAD];
    unsigned Wh2[64 * XPAD], Wl2[64 * XPAD];
    unsigned Xh[128 * XPAD], Xl[128 * XPAD];
    float W3[128];                // [k][2]
    float b1[64], b2[64], b0[64], Gg[64];
    float b3[2];
    float epart[8];
};
#define PAIR_SMEM_BYTES ((int)sizeof(PairSmem))

__device__ __forceinline__ void mma_layer(unsigned* __restrict__ Xh,
                                          unsigned* __restrict__ Xl,
                                          const unsigned* __restrict__ Wh,
                                          const unsigned* __restrict__ Wl,
                                          const float* __restrict__ bias,
                                          int w, int lane) {
    int r = lane >> 2, c = lane & 3;
    float acc[8][4];
#pragma unroll
    for (int nt = 0; nt < 8; ++nt) {
        float bv0 = bias[nt * 8 + 2 * c], bv1 = bias[nt * 8 + 2 * c + 1];
        acc[nt][0] = bv0; acc[nt][1] = bv1; acc[nt][2] = bv0; acc[nt][3] = bv1;
    }
    const unsigned* XhA = Xh + (w * 16 + r) * XPAD;
    const unsigned* XhB = XhA + 8 * XPAD;
    const unsigned* XlA = Xl + (w * 16 + r) * XPAD;
    const unsigned* XlB = XlA + 8 * XPAD;
#pragma unroll
    for (int s = 0; s < 4; ++s) {
        unsigned ah[4] = {XhA[s * 8 + c], XhB[s * 8 + c],
                          XhA[s * 8 + c + 4], XhB[s * 8 + c + 4]};
        unsigned al[4] = {XlA[s * 8 + c], XlB[s * 8 + c],
                          XlA[s * 8 + c + 4], XlB[s * 8 + c + 4]};
#pragma unroll
        for (int nt = 0; nt < 8; ++nt) {
            const unsigned* wh = Wh + (nt * 8 + r) * XPAD + s * 8;
            const unsigned* wl = Wl + (nt * 8 + r) * XPAD + s * 8;
            unsigned bh[2] = {wh[c], wh[c + 4]};
            unsigned bl[2] = {wl[c], wl[c + 4]};
            mma_bf16(acc[nt], ah, bh);   // x_hi * w_hi
            mma_bf16(acc[nt], al, bh);   // x_lo * w_hi
            mma_bf16(acc[nt], ah, bl);   // x_hi * w_lo
        }
    }
    __syncwarp();   // own-strip rows only; warp-local handoff
    unsigned* XhO = Xh + (w * 16 + r) * XPAD;
    unsigned* XhO8 = XhO + 8 * XPAD;
    unsigned* XlO = Xl + (w * 16 + r) * XPAD;
    unsigned* XlO8 = XlO + 8 * XPAD;
#pragma unroll
    for (int nt = 0; nt < 8; ++nt) {
        int kw = nt * 4 + c;
        float t0 = my_tanh(acc[nt][0]), t1 = my_tanh(acc[nt][1]);
        float t2 = my_tanh(acc[nt][2]), t3 = my_tanh(acc[nt][3]);
        __nv_bfloat16 h0 = __float2bfloat16(t0), h1 = __float2bfloat16(t1);
        __nv_bfloat16 h2 = __float2bfloat16(t2), h3 = __float2bfloat16(t3);
        XhO[kw] = pack_bf(h0, h1);
        XlO[kw] = pack_bf(__float2bfloat16(t0 - __bfloat162float(h0)),
                          __float2bfloat16(t1 - __bfloat162float(h1)));
        XhO8[kw] = pack_bf(h2, h3);
        XlO8[kw] = pack_bf(__float2bfloat16(t2 - __bfloat162float(h2)),
                           __float2bfloat16(t3 - __bfloat162float(h3)));
    }
    __syncwarp();
}

__global__ __launch_bounds__(256, 2) void pair_kernel(
    const float* __restrict__ aw1, const float* __restrict__ ab1,
    const float* __restrict__ aw2, const float* __restrict__ ab2,
    const float* __restrict__ aw3, const float* __restrict__ ab3,
    const float* __restrict__ ab0, const int* __restrict__ dimp) {
    extern __shared__ __align__(16) char smem_raw[];
    PairSmem* sm = (PairSmem*)smem_raw;
    int dim = read_dim(dimp);
    int p0 = blockIdx.x * BLKP;
    if (p0 >= dim) return;               // uniform block exit
    int b = blockIdx.y, t = threadIdx.x;

    // ---- stage weights as bf16 hi/lo words [n][kword] ----
#pragma unroll
    for (int i = 0; i < 16; ++i) {
        int e = t + 256 * i;
        int k = e >> 6, n = e & 63;
        int wi = (n * XPAD + (k >> 1)) * 2 + (k & 1);
        float w1v = aw1[e], w2v = aw2[e];
        __nv_bfloat16 h1 = __float2bfloat16(w1v);
        ((__nv_bfloat16*)sm->Wh1)[wi] = h1;
        ((__nv_bfloat16*)sm->Wl1)[wi] = __float2bfloat16(w1v - __bfloat162float(h1));
        __nv_bfloat16 h2 = __float2bfloat16(w2v);
        ((__nv_bfloat16*)sm->Wh2)[wi] = h2;
        ((__nv_bfloat16*)sm->Wl2)[wi] = __float2bfloat16(w2v - __bfloat162float(h2));
    }
    if (t < 64) {
        sm->b1[t] = ab1[t];
        sm->b2[t] = ab2[t];
        sm->b0[t] = ab0[t];
        sm->Gg[t] = d_Gg[b * 64 + t];
        sm->W3[2 * t + 0] = aw3[2 * t + 0];
        sm->W3[2 * t + 1] = aw3[2 * t + 1];
    }
    if (t < 2) sm->b3[t] = ab3[t];
    __syncthreads();

    // shift SA = sum_k |W3[k][0]|  (logit part <= SA since |h| < 1)
    float SA = 0.f;
#pragma unroll
    for (int k = 0; k < 64; ++k) SA += fabsf(sm->W3[2 * k]);

    // ---- layer 0: 2 threads per pair, each builds 32 features as hi/lo words ----
    {
        int lp = t >> 1, half = t & 1;
        int p = p0 + lp;
        int cnt = d_count[b];
        int kb = half * 32;
        unsigned* xh = sm->Xh + lp * XPAD + half * 16;
        unsigned* xl = sm->Xl + lp * XPAD + half * 16;
        float v[32];
        if (p < cnt && p < dim) {
            int q = d_order[b * DIMMAX + p];
            int i1 = q / Nn, i2 = q - i1 * Nn;
            const float4* Ga = (const float4*)(d_A + ((size_t)(b * Nn + i1)) * 64 + kb);
            const float4* Cc = (const float4*)(d_C + ((size_t)(b * Nn + i2)) * 64 + kb);
#pragma unroll
            for (int kk = 0; kk < 8; ++kk) {
                float4 a = Ga[kk], c4 = Cc[kk];
                int k = kb + 4 * kk;
                v[4 * kk + 0] = my_tanh(sm->Gg[k + 0] + a.x + c4.x);
                v[4 * kk + 1] = my_tanh(sm->Gg[k + 1] + a.y + c4.y);
                v[4 * kk + 2] = my_tanh(sm->Gg[k + 2] + a.z + c4.z);
                v[4 * kk + 3] = my_tanh(sm->Gg[k + 3] + a.w + c4.w);
            }
        } else {
            // invalid / out-of-range: zeroed input -> pre-activation = b0
#pragma unroll
            for (int kk = 0; kk < 32; ++kk) v[kk] = my_tanh(sm->b0[kb + kk]);
        }
#pragma unroll
        for (int kk2 = 0; kk2 < 16; ++kk2) {
            float v0 = v[2 * kk2], v1 = v[2 * kk2 + 1];
            __nv_bfloat16 h0 = __float2bfloat16(v0), h1 = __float2bfloat16(v1);
            xh[kk2] = pack_bf(h0, h1);
            xl[kk2] = pack_bf(__float2bfloat16(v0 - __bfloat162float(h0)),
                              __float2bfloat16(v1 - __bfloat162float(h1)));
        }
    }
    __syncwarp();

    int w = t >> 5, lane = t & 31;
    mma_layer(sm->Xh, sm->Xl, sm->Wh1, sm->Wl1, sm->b1, w, lane);
    mma_layer(sm->Xh, sm->Xl, sm->Wh2, sm->Wl2, sm->b2, w, lane);

    // ---- layer 3 + block partial softmax sum ----
    float ev = 0.f;
    {
        int lp = t >> 1, half = t & 1;
        int p = p0 + lp;
        const unsigned* xh = sm->Xh + lp * XPAD + half * 16;
        const unsigned* xl = sm->Xl + lp * XPAD + half * 16;
        float lg = 0.f, bq = 0.f;
        int kb = half * 32;
#pragma unroll
        for (int kk2 = 0; kk2 < 16; ++kk2) {
            __nv_bfloat162 hh = *reinterpret_cast<const __nv_bfloat162*>(xh + kk2);
            __nv_bfloat162 ll = *reinterpret_cast<const __nv_bfloat162*>(xl + kk2);
            float h0 = __bfloat162float(hh.x) + __bfloat162float(ll.x);
            float h1 = __bfloat162float(hh.y) + __bfloat162float(ll.y);
            int k = kb + 2 * kk2;
            lg += h0 * sm->W3[2 * k + 0] + h1 * sm->W3[2 * k + 2];
            bq += h0 * sm->W3[2 * k + 1] + h1 * sm->W3[2 * k + 3];
        }
        lg += __shfl_xor_sync(0xffffffffu, lg, 1);
        bq += __shfl_xor_sync(0xffffffffu, bq, 1);
        if (half == 0 && p < dim) {
            // e = exp(logit - (b3 + SA)); softmax is shift-invariant
            float e = __expf(lg - SA);
            d_logit[b * DIMMAX + p] = e;
            d_sig[b * DIMMAX + p] = 1.0f / (1.0f + __expf(-(bq + sm->b3[1])));
            ev = e;
        }
    }
    // block-level sum of e -> atomic into d_esum[b]
#pragma unroll
    for (int o = 16; o; o >>= 1) ev += __shfl_xor_sync(0xffffffffu, ev, o);
    if (lane == 0) sm->epart[w] = ev;
    __syncthreads();
    if (t == 0) {
        float s2 = 0.f;
#pragma unroll
        for (int i = 0; i < 8; ++i) s2 += sm->epart[i];
        atomicAdd(&d_esum[b], s2);
    }
}

// ---------------- kernel 3: wide normalize + scatter ----------------
__global__ void scatter_kernel(float* __restrict__ out, const int* __restrict__ dimp) {
    int dim = read_dim(dimp);
    int b = blockIdx.y;
    int p = blockIdx.x * 256 + threadIdx.x;
    if (p >= dim) return;
    if (p >= d_count[b]) return;  // valid == 0 -> contributes zeros only
    float inv = 1.0f / d_esum[b];
    int q = d_order[b * DIMMAX + p];
    float pi = d_logit[b * DIMMAX + p] * inv;
    float sg = d_sig[b * DIMMAX + p];
    float* ob = out + (size_t)b * 20000;
    ob[q] = pi * sg;
    ob[10000 + q] = pi * (1.0f - sg);
}

// ---------------- launcher (3 launches, single stream) ----------------
extern "C" void kernel_launch(void* const* d_in, const int* in_sizes, int n_in,
                              void* d_out, int out_size) {
    const float* emb = (const float*)d_in[0];
    const int* dimp;
    int base;
    if (n_in >= 18 && in_sizes[1] == 1) {   // dict order: emb, dim, actor..., critic...
        dimp = (const int*)d_in[1];
        base = 2;
    } else {                                // signature order: emb, actor..., critic..., dim
        dimp = (const int*)d_in[n_in - 1];
        base = 1;
    }
    const float* aw0 = (const float*)d_in[base + 0];
    const float* ab0 = (const float*)d_in[base + 1];
    const float* aw1 = (const float*)d_in[base + 2];
    const float* ab1 = (const float*)d_in[base + 3];
    const float* aw2 = (const float*)d_in[base + 4];
    const float* ab2 = (const float*)d_in[base + 5];
    const float* aw3 = (const float*)d_in[base + 6];
    const float* ab3 = (const float*)d_in[base + 7];
    const float* cw0 = (const float*)d_in[base + 8];
    const float* cb0 = (const float*)d_in[base + 9];
    const float* cw1 = (const float*)d_in[base + 10];
    const float* cb1 = (const float*)d_in[base + 11];
    const float* cw2 = (const float*)d_in[base + 12];
    const float* cb2 = (const float*)d_in[base + 13];
    const float* cw3 = (const float*)d_in[base + 14];
    const float* cb3 = (const float*)d_in[base + 15];

    float* out = (float*)d_out;
    int voff = out_size - Bz;  // value slot after the filled region (expect 640000)

    static int init_done = 0;
    if (!init_done) {
        cudaFuncSetAttribute(pair_kernel, cudaFuncAttributeMaxDynamicSharedMemorySize,
                             PAIR_SMEM_BYTES);
        cudaFuncSetAttribute(prep_kernel, cudaFuncAttributeMaxDynamicSharedMemorySize,
                             PREP_SMEM);
        init_done = 1;
    }

    prep_kernel<<<dim3(Bz, 23), 256, PREP_SMEM>>>(emb, aw0, ab0, cw0, cb0, cw1, cb1,
                                                  cw2, cb2, cw3, cb3, out, voff, dimp);
    pair_kernel<<<dim3(PBLK, Bz), 256, PAIR_SMEM_BYTES>>>(aw1, ab1, aw2, ab2, aw3, ab3,
                                                          ab0, dimp);
    scatter_kernel<<<dim3(40, Bz), 256>>>(out, dimp);
}

// round 10
// speedup vs baseline: 1.4896x; 1.2103x over previous
#include <cuda_runtime.h>
#include <cuda_bf16.h>
#include <cstdint>
#include <math.h>

#define Bz     32
#define Nn     100
#define Ff     514
#define FE     614      // 514 feats + 100 mask cols
#define ROWSE  101
#define NN2    10000
#define DIMMAX 10000
#define BLKP   128      // pairs per block in pair kernel
#define PBLK   79       // ceil(DIMMAX/128)
#define XPAD   36
#define WSTR   12       // word stride in ac GEMM smem (12 ≡ 4 mod 32 -> conflict-free)

// ---------------- scratch (static device globals; no allocation) ----------------
__device__ int   d_order[Bz * DIMMAX];
__device__ int   d_count[Bz];
__device__ float d_Gg[Bz * 64];
__device__ float d_A[Bz * Nn * 64];
__device__ float d_C[Bz * Nn * 64];
__device__ float d_logit[Bz * DIMMAX];   // holds e = exp(logit - shift)
__device__ float d_sig[Bz * DIMMAX];
__device__ float d_esum[Bz];

// ---------------- small helpers ----------------
__device__ __forceinline__ int read_dim(const int* p) {
    int v = *p;
    if (v < 1 || v > DIMMAX) {            // safety: tolerate float-encoded scalar
        float f = __int_as_float(v);
        v = (int)f;
    }
    if (v < 0) v = 0;
    if (v > DIMMAX) v = DIMMAX;
    return v;
}

__device__ __forceinline__ float my_tanh(float x) {
    // tanh(x) = 1 - 2/(exp(2x)+1)   (exact identity; __expf rel err ~2^-22)
    float e = __expf(2.0f * x);
    return 1.0f - __fdividef(2.0f, e + 1.0f);
}

__device__ __forceinline__ unsigned pack_bf(__nv_bfloat16 a, __nv_bfloat16 b) {
    __nv_bfloat162 v;
    v.x = a;  // low half
    v.y = b;  // high half
    return *reinterpret_cast<unsigned*>(&v);
}

__device__ __forceinline__ void split_word(float a, float b, unsigned& hw, unsigned& lw) {
    __nv_bfloat16 ha = __float2bfloat16(a), hb = __float2bfloat16(b);
    hw = pack_bf(ha, hb);
    lw = pack_bf(__float2bfloat16(a - __bfloat162float(ha)),
                 __float2bfloat16(b - __bfloat162float(hb)));
}

__device__ __forceinline__ void mma_bf16(float (&d)[4], const unsigned (&a)[4],
                                         const unsigned (&b)[2]) {
    asm volatile(
        "mma.sync.aligned.m16n8k16.row.col.f32.bf16.bf16.f32 "
        "{%0,%1,%2,%3}, {%4,%5,%6,%7}, {%8,%9}, {%0,%1,%2,%3};"
        : "+f"(d[0]), "+f"(d[1]), "+f"(d[2]), "+f"(d[3])
        : "r"(a[0]), "r"(a[1]), "r"(a[2]), "r"(a[3]), "r"(b[0]), "r"(b[1]));
}

// ================= prep kernel: ac-mma(4x32) / scan / head / zero ===============
// dynamic smem: 2 buffers x (128 W + 32 A rows) x 12 words x 2 (hi,lo) = 30720B
#define PREP_SMEM (2 * 320 * WSTR * 4)

__device__ void scan_role(const float* __restrict__ emb, int b, int dim, char* sh) {
    int t = threadIdx.x;           // 256
    int lane = t & 31, w = t >> 5; // 8 warps
    unsigned* bal = (unsigned*)sh;         // [320]
    int* pre = (int*)(sh + 320 * 4);       // [320]
#pragma unroll
    for (int c = 0; c < 40; ++c) {
        int idx = c * 256 + t;
        int flag = 0;
        if (idx < NN2) {
            int i = idx / Nn, j = idx - i * Nn;
            flag = emb[(size_t)(b * ROWSE + 1 + i) * FE + Ff + j] > 0.5f;
        }
        unsigned bl = __ballot_sync(0xffffffffu, flag);
        if (lane == 0) bal[c * 8 + w] = bl;
    }
    __syncthreads();
    if (t < 32) {
        int loc[10];
        int s = 0;
#pragma unroll
        for (int k = 0; k < 10; ++k) {
            int v = __popc(bal[lane * 10 + k]);
            loc[k] = s;
            s += v;
        }
        int p = s;
#pragma unroll
        for (int o = 1; o < 32; o <<= 1) {
            int n = __shfl_up_sync(0xffffffffu, p, o);
            if (lane >= o) p += n;
        }
        int off = p - s;
#pragma unroll
        for (int k = 0; k < 10; ++k) pre[lane * 10 + k] = off + loc[k];
        if (lane == 31) d_count[b] = p;
    }
    __syncthreads();
#pragma unroll
    for (int c = 0; c < 40; ++c) {
        unsigned bl = bal[c * 8 + w];
        if ((bl >> lane) & 1u) {
            int rank = pre[c * 8 + w] + __popc(bl & ((1u << lane) - 1u));
            if (rank < dim) d_order[b * DIMMAX + rank] = c * 256 + t;
        }
    }
}

__device__ void head_role(const float* __restrict__ emb,
                          const float* __restrict__ aw0, const float* __restrict__ ab0,
                          const float* __restrict__ cw0, const float* __restrict__ cb0,
                          const float* __restrict__ cw1, const float* __restrict__ cb1,
                          const float* __restrict__ cw2, const float* __restrict__ cb2,
                          const float* __restrict__ cw3, const float* __restrict__ cb3,
                          float* __restrict__ out, int voff, int b, char* sh) {
    float* row = (float*)sh;              // [516]
    float* part = row + 516;              // [256]
    float* ha = part + 256;               // [64]
    float* hb = ha + 64;                  // [64]
    int t = threadIdx.x;                  // 256
    for (int k = t; k < Ff; k += 256) row[k] = emb[(size_t)b * ROWSE * FE + k];
    __syncthreads();
    int j = t & 63, ks = t >> 6;  // 4-way k split
    {
        float acc = 0.f;
        for (int k = ks; k < Ff; k += 4) acc += row[k] * aw0[(size_t)k * 64 + j];
        part[t] = acc;
    }
    __syncthreads();
    if (t < 64) {
        float s = ab0[j] + part[j] + part[64 + j] + part[128 + j] + part[192 + j];
        d_Gg[b * 64 + j] = s;
    }
    __syncthreads();
    {
        float acc = 0.f;
        for (int k = ks; k < Ff; k += 4) acc += row[k] * cw0[(size_t)k * 64 + j];
        part[t] = acc;
    }
    __syncthreads();
    if (t < 64) {
        float s = cb0[j] + part[j] + part[64 + j] + part[128 + j] + part[192 + j];
        ha[j] = my_tanh(s);
    }
    __syncthreads();
    if (t < 64) {
        float acc = cb1[t];
        for (int k = 0; k < 64; ++k) acc += ha[k] * cw1[k * 64 + t];
        hb[t] = my_tanh(acc);
    }
    __syncthreads();
    if (t < 64) {
        float acc = cb2[t];
        for (int k = 0; k < 64; ++k) acc += hb[k] * cw2[k * 64 + t];
        ha[t] = my_tanh(acc);
    }
    __syncthreads();
    if (t == 0) {
        float v = cb3[0];
        for (int k = 0; k < 64; ++k) v += ha[k] * cw3[k];
        out[voff + b] = v;
    }
}

// [A|C] = nodes[3200,514] @ [W0_A | W0_C] as bf16 3-term-split tensor-core GEMM.
// Tile: 32 rows x 128 cols, K padded 514 -> 528 (33 x k16 chunks, zero tail).
__device__ void ac_mma_role(const float* __restrict__ emb,
                            const float* __restrict__ w0, int tile, char* sh) {
    int t = threadIdx.x;   // 256
    unsigned* buf = (unsigned*)sh;                 // 2 x 3840 words
    const float* wA = w0 + (size_t)Ff * 64;        // A weights [514][64]
    const float* wC = wA + (size_t)Ff * 64;        // C weights [514][64]
    int m0 = tile * 32;

    // A staging slot: row = t>>3 (0..31), word = t&7 (k pair)
    int arow = t >> 3, aword = t & 7;
    int gr = m0 + arow;
    int bb = gr / Nn, node = gr - bb * Nn;
    const float* asrc = emb + (size_t)(bb * ROWSE + 1 + node) * FE;

    float wreg[8];
    float2 areg;
    const int BUFW = 320 * WSTR;

#define AC_LOAD(kb)                                                          \
    do {                                                                     \
        _Pragma("unroll") for (int i = 0; i < 4; ++i) {                      \
            int e = t + 256 * i;                                             \
            int n = e & 127, wd = e >> 7;                                    \
            int k0 = (kb) + 2 * wd;                                          \
            const float* src = (n < 64) ? (wA + n) : (wC + (n - 64));        \
            wreg[2 * i] = (k0 < Ff) ? src[(size_t)k0 * 64] : 0.f;            \
            wreg[2 * i + 1] = (k0 + 1 < Ff) ? src[(size_t)(k0 + 1) * 64] : 0.f; \
        }                                                                    \
        int ka = (kb) + 2 * aword;                                           \
        areg = make_float2(0.f, 0.f);                                        \
        if (ka < Ff) {                                                       \
            areg = *(const float2*)(asrc + ka);                              \
            if (ka + 1 >= Ff) areg.y = 0.f;                                  \
        }                                                                    \
    } while (0)

#define AC_STORE(dst)                                                        \
    do {                                                                     \
        unsigned* Wh_ = (dst);                                               \
        unsigned* Wl_ = (dst) + 128 * WSTR;                                  \
        unsigned* Ah_ = (dst) + 256 * WSTR;                                  \
        unsigned* Al_ = Ah_ + 32 * WSTR;                                     \
        _Pragma("unroll") for (int i = 0; i < 4; ++i) {                      \
            int e = t + 256 * i;                                             \
            int n = e & 127, wd = e >> 7;                                    \
            unsigned hw, lw;                                                 \
            split_word(wreg[2 * i], wreg[2 * i + 1], hw, lw);                \
            Wh_[n * WSTR + wd] = hw;                                         \
            Wl_[n * WSTR + wd] = lw;                                         \
        }                                                                    \
        unsigned hw2, lw2;                                                   \
        split_word(areg.x, areg.y, hw2, lw2);                                \
        Ah_[arow * WSTR + aword] = hw2;                                      \
        Al_[arow * WSTR + aword] = lw2;                                      \
    } while (0)

    AC_LOAD(0);
    AC_STORE(buf);
    __syncthreads();

    int w = t >> 5, lane = t & 31;
    int r = lane >> 2, c = lane & 3;
    int ms = (w & 1) * 16;       // m-strip base within tile
    int ng = (w >> 1) * 32;      // n-group base (4 n8 tiles)

    float acc[4][4];
#pragma unroll
    for (int nt = 0; nt < 4; ++nt)
#pragma unroll
        for (int i2 = 0; i2 < 4; ++i2) acc[nt][i2] = 0.f;

    for (int kc = 0; kc < 33; ++kc) {
        unsigned* cur = buf + (kc & 1) * BUFW;
        unsigned* alt = buf + ((kc & 1) ^ 1) * BUFW;
        if (kc < 32) AC_LOAD((kc + 1) * 16);
        const unsigned* Wh = cur;
        const unsigned* Wl = cur + 128 * WSTR;
        const unsigned* Ah = cur + 256 * WSTR;
        const unsigned* Al = Ah + 32 * WSTR;
        const unsigned* aha = Ah + (ms + r) * WSTR;
        const unsigned* ala = Al + (ms + r) * WSTR;
        unsigned ah[4] = {aha[c], aha[8 * WSTR + c], aha[c + 4], aha[8 * WSTR + c + 4]};
        unsigned al[4] = {ala[c], ala[8 * WSTR + c], ala[c + 4], ala[8 * WSTR + c + 4]};
#pragma unroll
        for (int nt = 0; nt < 4; ++nt) {
            const unsigned* wh = Wh + (ng + nt * 8 + r) * WSTR;
            const unsigned* wl = Wl + (ng + nt * 8 + r) * WSTR;
            unsigned bh[2] = {wh[c], wh[c + 4]};
            unsigned bl[2] = {wl[c], wl[c + 4]};
            mma_bf16(acc[nt], ah, bh);   // a_hi * w_hi
            mma_bf16(acc[nt], al, bh);   // a_lo * w_hi
            mma_bf16(acc[nt], ah, bl);   // a_hi * w_lo
        }
        if (kc < 32) AC_STORE(alt);
        __syncthreads();
    }
#undef AC_LOAD
#undef AC_STORE

    // epilogue: fp32 results -> d_A / d_C
#pragma unroll
    for (int nt = 0; nt < 4; ++nt) {
        int j = ng + nt * 8 + 2 * c;
        int gr0 = m0 + ms + r, gr1 = gr0 + 8;
        float* dst = (j < 64) ? d_A : d_C;
        int jj = (j < 64) ? j : j - 64;
        *(float2*)(dst + (size_t)gr0 * 64 + jj) = make_float2(acc[nt][0], acc[nt][1]);
        *(float2*)(dst + (size_t)gr1 * 64 + jj) = make_float2(acc[nt][2], acc[nt][3]);
    }
}

__device__ void zero_role(float* __restrict__ out, int b) {
    float4 z = make_float4(0.f, 0.f, 0.f, 0.f);
    float4* ob = (float4*)(out + (size_t)b * 20000);
    for (int i = threadIdx.x; i < 5000; i += 256) ob[i] = z;
    if (threadIdx.x == 0) d_esum[b] = 0.f;
}

__global__ void prep_kernel(const float* __restrict__ emb,
                            const float* __restrict__ aw0, const float* __restrict__ ab0,
                            const float* __restrict__ cw0, const float* __restrict__ cb0,
                            const float* __restrict__ cw1, const float* __restrict__ cb1,
                            const float* __restrict__ cw2, const float* __restrict__ cb2,
                            const float* __restrict__ cw3, const float* __restrict__ cb3,
                            float* __restrict__ out, int voff,
                            const int* __restrict__ dimp) {
    extern __shared__ __align__(16) char sh[];
    int b = blockIdx.x;
    int role = blockIdx.y;
    if (role < 4) {
        int tile = role * 32 + b;
        if (tile < 100) ac_mma_role(emb, aw0, tile, sh);
    } else if (role == 4) {
        scan_role(emb, b, read_dim(dimp), sh);
    } else if (role == 5) {
        head_role(emb, aw0, ab0, cw0, cb0, cw1, cb1, cw2, cb2, cw3, cb3, out, voff, b, sh);
    } else {
        zero_role(out, b);
    }
}

// ============== pair kernel v7: bf16 m16n8k16 MMA, 3-term split =================
// 128 pairs/block, 8 warps; warp owns a 16-row m-strip through both layers.
// X, W stored as bf16x2 words (hi + lo arrays), XPAD=36 => conflict-free frags.
struct PairSmem {
    unsigned Wh1[64 * XPAD], Wl1[64 * XPAD];
    unsigned Wh2[64 * XPAD], Wl2[64 * XPAD];
    unsigned Xh[128 * XPAD], Xl[128 * XPAD];
    float W3[128];                // [k][2]
    float b1[64], b2[64], b0[64], Gg[64];
    float b3[2];
    float epart[8];
};
#define PAIR_SMEM_BYTES ((int)sizeof(PairSmem))

__device__ __forceinline__ void mma_layer(unsigned* __restrict__ Xh,
                                          unsigned* __restrict__ Xl,
                                          const unsigned* __restrict__ Wh,
                                          const unsigned* __restrict__ Wl,
                                          const float* __restrict__ bias,
                                          int w, int lane) {
    int r = lane >> 2, c = lane & 3;
    float acc[8][4];
#pragma unroll
    for (int nt = 0; nt < 8; ++nt) {
        float bv0 = bias[nt * 8 + 2 * c], bv1 = bias[nt * 8 + 2 * c + 1];
        acc[nt][0] = bv0; acc[nt][1] = bv1; acc[nt][2] = bv0; acc[nt][3] = bv1;
    }
    const unsigned* XhA = Xh + (w * 16 + r) * XPAD;
    const unsigned* XhB = XhA + 8 * XPAD;
    const unsigned* XlA = Xl + (w * 16 + r) * XPAD;
    const unsigned* XlB = XlA + 8 * XPAD;
#pragma unroll
    for (int s = 0; s < 4; ++s) {
        unsigned ah[4] = {XhA[s * 8 + c], XhB[s * 8 + c],
                          XhA[s * 8 + c + 4], XhB[s * 8 + c + 4]};
        unsigned al[4] = {XlA[s * 8 + c], XlB[s * 8 + c],
                          XlA[s * 8 + c + 4], XlB[s * 8 + c + 4]};
#pragma unroll
        for (int nt = 0; nt < 8; ++nt) {
            const unsigned* wh = Wh + (nt * 8 + r) * XPAD + s * 8;
            const unsigned* wl = Wl + (nt * 8 + r) * XPAD + s * 8;
            unsigned bh[2] = {wh[c], wh[c + 4]};
            unsigned bl[2] = {wl[c], wl[c + 4]};
            mma_bf16(acc[nt], ah, bh);   // x_hi * w_hi
            mma_bf16(acc[nt], al, bh);   // x_lo * w_hi
            mma_bf16(acc[nt], ah, bl);   // x_hi * w_lo
        }
    }
    __syncwarp();   // own-strip rows only; warp-local handoff
    unsigned* XhO = Xh + (w * 16 + r) * XPAD;
    unsigned* XhO8 = XhO + 8 * XPAD;
    unsigned* XlO = Xl + (w * 16 + r) * XPAD;
    unsigned* XlO8 = XlO + 8 * XPAD;
#pragma unroll
    for (int nt = 0; nt < 8; ++nt) {
        int kw = nt * 4 + c;
        float t0 = my_tanh(acc[nt][0]), t1 = my_tanh(acc[nt][1]);
        float t2 = my_tanh(acc[nt][2]), t3 = my_tanh(acc[nt][3]);
        __nv_bfloat16 h0 = __float2bfloat16(t0), h1 = __float2bfloat16(t1);
        __nv_bfloat16 h2 = __float2bfloat16(t2), h3 = __float2bfloat16(t3);
        XhO[kw] = pack_bf(h0, h1);
        XlO[kw] = pack_bf(__float2bfloat16(t0 - __bfloat162float(h0)),
                          __float2bfloat16(t1 - __bfloat162float(h1)));
        XhO8[kw] = pack_bf(h2, h3);
        XlO8[kw] = pack_bf(__float2bfloat16(t2 - __bfloat162float(h2)),
                           __float2bfloat16(t3 - __bfloat162float(h3)));
    }
    __syncwarp();
}

__global__ __launch_bounds__(256, 2) void pair_kernel(
    const float* __restrict__ aw1, const float* __restrict__ ab1,
    const float* __restrict__ aw2, const float* __restrict__ ab2,
    const float* __restrict__ aw3, const float* __restrict__ ab3,
    const float* __restrict__ ab0, const int* __restrict__ dimp) {
    extern __shared__ __align__(16) char smem_raw[];
    PairSmem* sm = (PairSmem*)smem_raw;
    int dim = read_dim(dimp);
    int p0 = blockIdx.x * BLKP;
    if (p0 >= dim) return;               // uniform block exit
    int b = blockIdx.y, t = threadIdx.x;

    // ---- stage weights as bf16 hi/lo words [n][kword] ----
#pragma unroll
    for (int i = 0; i < 16; ++i) {
        int e = t + 256 * i;
        int k = e >> 6, n = e & 63;
        int wi = (n * XPAD + (k >> 1)) * 2 + (k & 1);
        float w1v = aw1[e], w2v = aw2[e];
        __nv_bfloat16 h1 = __float2bfloat16(w1v);
        ((__nv_bfloat16*)sm->Wh1)[wi] = h1;
        ((__nv_bfloat16*)sm->Wl1)[wi] = __float2bfloat16(w1v - __bfloat162float(h1));
        __nv_bfloat16 h2 = __float2bfloat16(w2v);
        ((__nv_bfloat16*)sm->Wh2)[wi] = h2;
        ((__nv_bfloat16*)sm->Wl2)[wi] = __float2bfloat16(w2v - __bfloat162float(h2));
    }
    if (t < 64) {
        sm->b1[t] = ab1[t];
        sm->b2[t] = ab2[t];
        sm->b0[t] = ab0[t];
        sm->Gg[t] = d_Gg[b * 64 + t];
        sm->W3[2 * t + 0] = aw3[2 * t + 0];
        sm->W3[2 * t + 1] = aw3[2 * t + 1];
    }
    if (t < 2) sm->b3[t] = ab3[t];
    __syncthreads();

    // shift SA = sum_k |W3[k][0]|  (logit part <= SA since |h| < 1)
    float SA = 0.f;
#pragma unroll
    for (int k = 0; k < 64; ++k) SA += fabsf(sm->W3[2 * k]);

    // ---- layer 0: 2 threads per pair, each builds 32 features as hi/lo words ----
    {
        int lp = t >> 1, half = t & 1;
        int p = p0 + lp;
        int cnt = d_count[b];
        int kb = half * 32;
        unsigned* xh = sm->Xh + lp * XPAD + half * 16;
        unsigned* xl = sm->Xl + lp * XPAD + half * 16;
        float v[32];
        if (p < cnt && p < dim) {
            int q = d_order[b * DIMMAX + p];
            int i1 = q / Nn, i2 = q - i1 * Nn;
            const float4* Ga = (const float4*)(d_A + ((size_t)(b * Nn + i1)) * 64 + kb);
            const float4* Cc = (const float4*)(d_C + ((size_t)(b * Nn + i2)) * 64 + kb);
#pragma unroll
            for (int kk = 0; kk < 8; ++kk) {
                float4 a = Ga[kk], c4 = Cc[kk];
                int k = kb + 4 * kk;
                v[4 * kk + 0] = my_tanh(sm->Gg[k + 0] + a.x + c4.x);
                v[4 * kk + 1] = my_tanh(sm->Gg[k + 1] + a.y + c4.y);
                v[4 * kk + 2] = my_tanh(sm->Gg[k + 2] + a.z + c4.z);
                v[4 * kk + 3] = my_tanh(sm->Gg[k + 3] + a.w + c4.w);
            }
        } else {
            // invalid / out-of-range: zeroed input -> pre-activation = b0
#pragma unroll
            for (int kk = 0; kk < 32; ++kk) v[kk] = my_tanh(sm->b0[kb + kk]);
        }
#pragma unroll
        for (int kk2 = 0; kk2 < 16; ++kk2) {
            float v0 = v[2 * kk2], v1 = v[2 * kk2 + 1];
            __nv_bfloat16 h0 = __float2bfloat16(v0), h1 = __float2bfloat16(v1);
            xh[kk2] = pack_bf(h0, h1);
            xl[kk2] = pack_bf(__float2bfloat16(v0 - __bfloat162float(h0)),
                              __float2bfloat16(v1 - __bfloat162float(h1)));
        }
    }
    __syncwarp();

    int w = t >> 5, lane = t & 31;
    mma_layer(sm->Xh, sm->Xl, sm->Wh1, sm->Wl1, sm->b1, w, lane);
    mma_layer(sm->Xh, sm->Xl, sm->Wh2, sm->Wl2, sm->b2, w, lane);

    // ---- layer 3 + block partial softmax sum ----
    float ev = 0.f;
    {
        int lp = t >> 1, half = t & 1;
        int p = p0 + lp;
        const unsigned* xh = sm->Xh + lp * XPAD + half * 16;
        const unsigned* xl = sm->Xl + lp * XPAD + half * 16;
        float lg = 0.f, bq = 0.f;
        int kb = half * 32;
#pragma unroll
        for (int kk2 = 0; kk2 < 16; ++kk2) {
            __nv_bfloat162 hh = *reinterpret_cast<const __nv_bfloat162*>(xh + kk2);
            __nv_bfloat162 ll = *reinterpret_cast<const __nv_bfloat162*>(xl + kk2);
            float h0 = __bfloat162float(hh.x) + __bfloat162float(ll.x);
            float h1 = __bfloat162float(hh.y) + __bfloat162float(ll.y);
            int k = kb + 2 * kk2;
            lg += h0 * sm->W3[2 * k + 0] + h1 * sm->W3[2 * k + 2];
            bq += h0 * sm->W3[2 * k + 1] + h1 * sm->W3[2 * k + 3];
        }
        lg += __shfl_xor_sync(0xffffffffu, lg, 1);
        bq += __shfl_xor_sync(0xffffffffu, bq, 1);
        if (half == 0 && p < dim) {
            // e = exp(logit - (b3 + SA)); softmax is shift-invariant
            float e = __expf(lg - SA);
            d_logit[b * DIMMAX + p] = e;
            d_sig[b * DIMMAX + p] = 1.0f / (1.0f + __expf(-(bq + sm->b3[1])));
            ev = e;
        }
    }
    // block-level sum of e -> atomic into d_esum[b]
#pragma unroll
    for (int o = 16; o; o >>= 1) ev += __shfl_xor_sync(0xffffffffu, ev, o);
    if (lane == 0) sm->epart[w] = ev;
    __syncthreads();
    if (t == 0) {
        float s2 = 0.f;
#pragma unroll
        for (int i = 0; i < 8; ++i) s2 += sm->epart[i];
        atomicAdd(&d_esum[b], s2);
    }
}

// ---------------- kernel 3: wide normalize + scatter ----------------
__global__ void scatter_kernel(float* __restrict__ out, const int* __restrict__ dimp) {
    int dim = read_dim(dimp);
    int b = blockIdx.y;
    int p = blockIdx.x * 256 + threadIdx.x;
    if (p >= dim) return;
    if (p >= d_count[b]) return;  // valid == 0 -> contributes zeros only
    float inv = 1.0f / d_esum[b];
    int q = d_order[b * DIMMAX + p];
    float pi = d_logit[b * DIMMAX + p] * inv;
    float sg = d_sig[b * DIMMAX + p];
    float* ob = out + (size_t)b * 20000;
    ob[q] = pi * sg;
    ob[10000 + q] = pi * (1.0f - sg);
}

// ---------------- launcher (3 launches, single stream) ----------------
extern "C" void kernel_launch(void* const* d_in, const int* in_sizes, int n_in,
                              void* d_out, int out_size) {
    const float* emb = (const float*)d_in[0];
    const int* dimp;
    int base;
    if (n_in >= 18 && in_sizes[1] == 1) {   // dict order: emb, dim, actor..., critic...
        dimp = (const int*)d_in[1];
        base = 2;
    } else {                                // signature order: emb, actor..., critic..., dim
        dimp = (const int*)d_in[n_in - 1];
        base = 1;
    }
    const float* aw0 = (const float*)d_in[base + 0];
    const float* ab0 = (const float*)d_in[base + 1];
    const float* aw1 = (const float*)d_in[base + 2];
    const float* ab1 = (const float*)d_in[base + 3];
    const float* aw2 = (const float*)d_in[base + 4];
    const float* ab2 = (const float*)d_in[base + 5];
    const float* aw3 = (const float*)d_in[base + 6];
    const float* ab3 = (const float*)d_in[base + 7];
    const float* cw0 = (const float*)d_in[base + 8];
    const float* cb0 = (const float*)d_in[base + 9];
    const float* cw1 = (const float*)d_in[base + 10];
    const float* cb1 = (const float*)d_in[base + 11];
    const float* cw2 = (const float*)d_in[base + 12];
    const float* cb2 = (const float*)d_in[base + 13];
    const float* cw3 = (const float*)d_in[base + 14];
    const float* cb3 = (const float*)d_in[base + 15];

    float* out = (float*)d_out;
    int voff = out_size - Bz;  // value slot after the filled region (expect 640000)

    static int init_done = 0;
    if (!init_done) {
        cudaFuncSetAttribute(pair_kernel, cudaFuncAttributeMaxDynamicSharedMemorySize,
                             PAIR_SMEM_BYTES);
        cudaFuncSetAttribute(prep_kernel, cudaFuncAttributeMaxDynamicSharedMemorySize,
                             PREP_SMEM);
        init_done = 1;
    }

    prep_kernel<<<dim3(Bz, 7), 256, PREP_SMEM>>>(emb, aw0, ab0, cw0, cb0, cw1, cb1,
                                                 cw2, cb2, cw3, cb3, out, voff, dimp);
    pair_kernel<<<dim3(PBLK, Bz), 256, PAIR_SMEM_BYTES>>>(aw1, ab1, aw2, ab2, aw3, ab3,
                                                          ab0, dimp);
    scatter_kernel<<<dim3(40, Bz), 256>>>(out, dimp);
}

// round 11
// speedup vs baseline: 1.5279x; 1.0257x over previous
#include <cuda_runtime.h>
#include <cuda_bf16.h>
#include <cstdint>
#include <math.h>

#define Bz     32
#define Nn     100
#define Ff     514
#define FE     614      // 514 feats + 100 mask cols
#define ROWSE  101
#define NN2    10000
#define DIMMAX 10000
#define BLKP   128      // pairs per block in pair kernel
#define PBLK   79       // ceil(DIMMAX/128)
#define XPAD   36
#define WSTR   12       // word stride in ac GEMM smem (12 ≡ 4 mod 32 -> conflict-free)

// ---------------- scratch (static device globals; no allocation) ----------------
__device__ int   d_order[Bz * DIMMAX];
__device__ int   d_count[Bz];
__device__ float d_Gg[Bz * 64];
__device__ float d_A[Bz * Nn * 64];
__device__ float d_C[Bz * Nn * 64];
__device__ float d_logit[Bz * DIMMAX];   // holds e = exp(logit - shift)
__device__ float d_sig[Bz * DIMMAX];
__device__ float d_esum[Bz];
__device__ uint4 d_Wpre4[2304];          // pair weights, split-bf16 padded layout

// ---------------- small helpers ----------------
__device__ __forceinline__ int read_dim(const int* p) {
    int v = *p;
    if (v < 1 || v > DIMMAX) {            // safety: tolerate float-encoded scalar
        float f = __int_as_float(v);
        v = (int)f;
    }
    if (v < 0) v = 0;
    if (v > DIMMAX) v = DIMMAX;
    return v;
}

// Eigen-style rational minimax tanh: 1 MUFU (rcp) instead of 2 (ex2+rcp).
__device__ __forceinline__ float my_tanh(float x) {
    x = fminf(fmaxf(x, -7.90531110763549805f), 7.90531110763549805f);
    float x2 = x * x;
    float p = fmaf(x2, -2.76076847742355e-16f, 2.00018790482477e-13f);
    p = fmaf(x2, p, -8.60467152213735e-11f);
    p = fmaf(x2, p, 5.12229709037114e-08f);
    p = fmaf(x2, p, 1.48572235717979e-05f);
    p = fmaf(x2, p, 6.37261928875436e-04f);
    p = fmaf(x2, p, 4.89352455891786e-03f);
    p = x * p;
    float q = fmaf(x2, 1.19825839466702e-06f, 1.18534705686654e-04f);
    q = fmaf(x2, q, 2.26843463243900e-03f);
    q = fmaf(x2, q, 4.89352518554385e-03f);
    return __fdividef(p, q);
}

__device__ __forceinline__ unsigned pack_bf(__nv_bfloat16 a, __nv_bfloat16 b) {
    __nv_bfloat162 v;
    v.x = a;  // low half
    v.y = b;  // high half
    return *reinterpret_cast<unsigned*>(&v);
}

__device__ __forceinline__ void split_word(float a, float b, unsigned& hw, unsigned& lw) {
    __nv_bfloat16 ha = __float2bfloat16(a), hb = __float2bfloat16(b);
    hw = pack_bf(ha, hb);
    lw = pack_bf(__float2bfloat16(a - __bfloat162float(ha)),
                 __float2bfloat16(b - __bfloat162float(hb)));
}

__device__ __forceinline__ void mma_bf16(float (&d)[4], const unsigned (&a)[4],
                                         const unsigned (&b)[2]) {
    asm volatile(
        "mma.sync.aligned.m16n8k16.row.col.f32.bf16.bf16.f32 "
        "{%0,%1,%2,%3}, {%4,%5,%6,%7}, {%8,%9}, {%0,%1,%2,%3};"
        : "+f"(d[0]), "+f"(d[1]), "+f"(d[2]), "+f"(d[3])
        : "r"(a[0]), "r"(a[1]), "r"(a[2]), "r"(a[3]), "r"(b[0]), "r"(b[1]));
}

// ================= prep kernel: ac-mma(4x32) / scan / head / zero+convert =======
// dynamic smem: 2 buffers x (128 W + 32 A rows) x 12 words x 2 (hi,lo) = 30720B
#define PREP_SMEM (2 * 320 * WSTR * 4)

__device__ void scan_role(const float* __restrict__ emb, int b, int dim, char* sh) {
    int t = threadIdx.x;           // 256
    int lane = t & 31, w = t >> 5; // 8 warps
    unsigned* bal = (unsigned*)sh;         // [320]
    int* pre = (int*)(sh + 320 * 4);       // [320]
    // phase 1: batched loads (20 in flight), then ballots
#pragma unroll
    for (int hf = 0; hf < 2; ++hf) {
        float v[20];
#pragma unroll
        for (int c2 = 0; c2 < 20; ++c2) {
            int c = hf * 20 + c2;
            int idx = c * 256 + t;
            float val = 0.f;
            if (idx < NN2) {
                int i = idx / Nn, j = idx - i * Nn;
                val = emb[(size_t)(b * ROWSE + 1 + i) * FE + Ff + j];
            }
            v[c2] = val;
        }
#pragma unroll
        for (int c2 = 0; c2 < 20; ++c2) {
            unsigned bl = __ballot_sync(0xffffffffu, v[c2] > 0.5f);
            if (lane == 0) bal[(hf * 20 + c2) * 8 + w] = bl;
        }
    }
    __syncthreads();
    if (t < 32) {
        int loc[10];
        int s = 0;
#pragma unroll
        for (int k = 0; k < 10; ++k) {
            int v = __popc(bal[lane * 10 + k]);
            loc[k] = s;
            s += v;
        }
        int p = s;
#pragma unroll
        for (int o = 1; o < 32; o <<= 1) {
            int n = __shfl_up_sync(0xffffffffu, p, o);
            if (lane >= o) p += n;
        }
        int off = p - s;
#pragma unroll
        for (int k = 0; k < 10; ++k) pre[lane * 10 + k] = off + loc[k];
        if (lane == 31) d_count[b] = p;
    }
    __syncthreads();
#pragma unroll
    for (int c = 0; c < 40; ++c) {
        unsigned bl = bal[c * 8 + w];
        if ((bl >> lane) & 1u) {
            int rank = pre[c * 8 + w] + __popc(bl & ((1u << lane) - 1u));
            if (rank < dim) d_order[b * DIMMAX + rank] = c * 256 + t;
        }
    }
}

__device__ void head_role(const float* __restrict__ emb,
                          const float* __restrict__ aw0, const float* __restrict__ ab0,
                          const float* __restrict__ cw0, const float* __restrict__ cb0,
                          const float* __restrict__ cw1, const float* __restrict__ cb1,
                          const float* __restrict__ cw2, const float* __restrict__ cb2,
                          const float* __restrict__ cw3, const float* __restrict__ cb3,
                          float* __restrict__ out, int voff, int b, char* sh) {
    float* row = (float*)sh;              // [516]
    float* part = row + 516;              // [256]
    float* ha = part + 256;               // [64]
    float* hb = ha + 64;                  // [64]
    int t = threadIdx.x;                  // 256
    for (int k = t; k < Ff; k += 256) row[k] = emb[(size_t)b * ROWSE * FE + k];
    __syncthreads();
    int j = t & 63, ks = t >> 6;  // 4-way k split
    {
        float acc = 0.f;
        for (int k = ks; k < Ff; k += 4) acc += row[k] * aw0[(size_t)k * 64 + j];
        part[t] = acc;
    }
    __syncthreads();
    if (t < 64) {
        float s = ab0[j] + part[j] + part[64 + j] + part[128 + j] + part[192 + j];
        d_Gg[b * 64 + j] = s;
    }
    __syncthreads();
    {
        float acc = 0.f;
        for (int k = ks; k < Ff; k += 4) acc += row[k] * cw0[(size_t)k * 64 + j];
        part[t] = acc;
    }
    __syncthreads();
    if (t < 64) {
        float s = cb0[j] + part[j] + part[64 + j] + part[128 + j] + part[192 + j];
        ha[j] = my_tanh(s);
    }
    __syncthreads();
    if (t < 64) {
        float acc = cb1[t];
        for (int k = 0; k < 64; ++k) acc += ha[k] * cw1[k * 64 + t];
        hb[t] = my_tanh(acc);
    }
    __syncthreads();
    if (t < 64) {
        float acc = cb2[t];
        for (int k = 0; k < 64; ++k) acc += hb[k] * cw2[k * 64 + t];
        ha[t] = my_tanh(acc);
    }
    __syncthreads();
    if (t == 0) {
        float v = cb3[0];
        for (int k = 0; k < 64; ++k) v += ha[k] * cw3[k];
        out[voff + b] = v;
    }
}

// [A|C] = nodes[3200,514] @ [W0_A | W0_C] as bf16 3-term-split tensor-core GEMM.
// Tile: 32 rows x 128 cols, K padded 514 -> 528 (33 x k16 chunks, zero tail).
// 2-chunk-ahead register prefetch to hide LDG latency.
__device__ void ac_mma_role(const float* __restrict__ emb,
                            const float* __restrict__ w0, int tile, char* sh) {
    int t = threadIdx.x;   // 256
    unsigned* buf = (unsigned*)sh;                 // 2 x 3840 words
    const float* wA = w0 + (size_t)Ff * 64;        // A weights [514][64]
    const float* wC = wA + (size_t)Ff * 64;        // C weights [514][64]
    int m0 = tile * 32;

    // A staging slot: row = t>>3 (0..31), word = t&7 (k pair)
    int arow = t >> 3, aword = t & 7;
    int gr = m0 + arow;
    int bb = gr / Nn, node = gr - bb * Nn;
    const float* asrc = emb + (size_t)(bb * ROWSE + 1 + node) * FE;

    float wreg[2][8];
    float2 areg[2];
    const int BUFW = 320 * WSTR;

#define AC_LOAD(sl, kb)                                                      \
    do {                                                                     \
        _Pragma("unroll") for (int i = 0; i < 4; ++i) {                      \
            int e = t + 256 * i;                                             \
            int n = e & 127, wd = e >> 7;                                    \
            int k0 = (kb) + 2 * wd;                                          \
            const float* src = (n < 64) ? (wA + n) : (wC + (n - 64));        \
            wreg[sl][2 * i] = (k0 < Ff) ? src[(size_t)k0 * 64] : 0.f;        \
            wreg[sl][2 * i + 1] = (k0 + 1 < Ff) ? src[(size_t)(k0 + 1) * 64] : 0.f; \
        }                                                                    \
        int ka = (kb) + 2 * aword;                                           \
        areg[sl] = make_float2(0.f, 0.f);                                    \
        if (ka < Ff) {                                                       \
            areg[sl] = *(const float2*)(asrc + ka);                          \
            if (ka + 1 >= Ff) areg[sl].y = 0.f;                              \
        }                                                                    \
    } while (0)

#define AC_STORE(sl, dst)                                                    \
    do {                                                                     \
        unsigned* Wh_ = (dst);                                               \
        unsigned* Wl_ = (dst) + 128 * WSTR;                                  \
        unsigned* Ah_ = (dst) + 256 * WSTR;                                  \
        unsigned* Al_ = Ah_ + 32 * WSTR;                                     \
        _Pragma("unroll") for (int i = 0; i < 4; ++i) {                      \
            int e = t + 256 * i;                                             \
            int n = e & 127, wd = e >> 7;                                    \
            unsigned hw, lw;                                                 \
            split_word(wreg[sl][2 * i], wreg[sl][2 * i + 1], hw, lw);        \
            Wh_[n * WSTR + wd] = hw;                                         \
            Wl_[n * WSTR + wd] = lw;                                         \
        }                                                                    \
        unsigned hw2, lw2;                                                   \
        split_word(areg[sl].x, areg[sl].y, hw2, lw2);                        \
        Ah_[arow * WSTR + aword] = hw2;                                      \
        Al_[arow * WSTR + aword] = lw2;                                      \
    } while (0)

    AC_LOAD(0, 0);
    AC_STORE(0, buf);
    AC_LOAD(0, 16);      // slot0 now holds chunk 1
    __syncthreads();

    int w = t >> 5, lane = t & 31;
    int r = lane >> 2, c = lane & 3;
    int ms = (w & 1) * 16;       // m-strip base within tile
    int ng = (w >> 1) * 32;      // n-group base (4 n8 tiles)

    float acc[4][4];
#pragma unroll
    for (int nt = 0; nt < 4; ++nt)
#pragma unroll
        for (int i2 = 0; i2 < 4; ++i2) acc[nt][i2] = 0.f;

#pragma unroll 2
    for (int kc = 0; kc < 33; ++kc) {
        unsigned* cur = buf + (kc & 1) * BUFW;
        unsigned* alt = buf + ((kc & 1) ^ 1) * BUFW;
        if (kc <= 30) AC_LOAD((kc + 1) & 1, (kc + 2) * 16);   // chunk kc+2
        const unsigned* Wh = cur;
        const unsigned* Wl = cur + 128 * WSTR;
        const unsigned* Ah = cur + 256 * WSTR;
        const unsigned* Al = Ah + 32 * WSTR;
        const unsigned* aha = Ah + (ms + r) * WSTR;
        const unsigned* ala = Al + (ms + r) * WSTR;
        unsigned ah[4] = {aha[c], aha[8 * WSTR + c], aha[c + 4], aha[8 * WSTR + c + 4]};
        unsigned al[4] = {ala[c], ala[8 * WSTR + c], ala[c + 4], ala[8 * WSTR + c + 4]};
#pragma unroll
        for (int nt = 0; nt < 4; ++nt) {
            const unsigned* wh = Wh + (ng + nt * 8 + r) * WSTR;
            const unsigned* wl = Wl + (ng + nt * 8 + r) * WSTR;
            unsigned bh[2] = {wh[c], wh[c + 4]};
            unsigned bl[2] = {wl[c], wl[c + 4]};
            mma_bf16(acc[nt], ah, bh);   // a_hi * w_hi
            mma_bf16(acc[nt], al, bh);   // a_lo * w_hi
            mma_bf16(acc[nt], ah, bl);   // a_hi * w_lo
        }
        if (kc <= 31) AC_STORE(kc & 1, alt);                  // chunk kc+1
        __syncthreads();
    }
#undef AC_LOAD
#undef AC_STORE

    // epilogue: fp32 results -> d_A / d_C
#pragma unroll
    for (int nt = 0; nt < 4; ++nt) {
        int j = ng + nt * 8 + 2 * c;
        int gr0 = m0 + ms + r, gr1 = gr0 + 8;
        float* dst = (j < 64) ? d_A : d_C;
        int jj = (j < 64) ? j : j - 64;
        *(float2*)(dst + (size_t)gr0 * 64 + jj) = make_float2(acc[nt][0], acc[nt][1]);
        *(float2*)(dst + (size_t)gr1 * 64 + jj) = make_float2(acc[nt][2], acc[nt][3]);
    }
}

// zero output slab + esum, and convert this block's slice of pair weights
__device__ void zero_role(float* __restrict__ out, int b,
                          const float* __restrict__ aw1,
                          const float* __restrict__ aw2) {
    float4 z = make_float4(0.f, 0.f, 0.f, 0.f);
    float4* ob = (float4*)(out + (size_t)b * 20000);
    int t = threadIdx.x;
    for (int i = t; i < 5000; i += 256) ob[i] = z;
    if (t == 0) d_esum[b] = 0.f;
    // convert slice: elements e in [b*128, b*128+128) of aw1 and aw2
    if (t < 128) {
        __nv_bfloat16* wp = (__nv_bfloat16*)d_Wpre4;
        int e = b * 128 + t;
        int k = e >> 6, n = e & 63;
        int ei = n * 72 + k;
        float w1v = aw1[e], w2v = aw2[e];
        __nv_bfloat16 h1 = __float2bfloat16(w1v);
        wp[0 * 4608 + ei] = h1;
        wp[1 * 4608 + ei] = __float2bfloat16(w1v - __bfloat162float(h1));
        __nv_bfloat16 h2 = __float2bfloat16(w2v);
        wp[2 * 4608 + ei] = h2;
        wp[3 * 4608 + ei] = __float2bfloat16(w2v - __bfloat162float(h2));
    }
}

__global__ void prep_kernel(const float* __restrict__ emb,
                            const float* __restrict__ aw0, const float* __restrict__ ab0,
                            const float* __restrict__ aw1, const float* __restrict__ aw2,
                            const float* __restrict__ cw0, const float* __restrict__ cb0,
                            const float* __restrict__ cw1, const float* __restrict__ cb1,
                            const float* __restrict__ cw2, const float* __restrict__ cb2,
                            const float* __restrict__ cw3, const float* __restrict__ cb3,
                            float* __restrict__ out, int voff,
                            const int* __restrict__ dimp) {
    extern __shared__ __align__(16) char sh[];
    int b = blockIdx.x;
    int role = blockIdx.y;
    if (role < 4) {
        int tile = role * 32 + b;
        if (tile < 100) ac_mma_role(emb, aw0, tile, sh);
    } else if (role == 4) {
        scan_role(emb, b, read_dim(dimp), sh);
    } else if (role == 5) {
        head_role(emb, aw0, ab0, cw0, cb0, cw1, cb1, cw2, cb2, cw3, cb3, out, voff, b, sh);
    } else {
        zero_role(out, b, aw1, aw2);
    }
}

// ============== pair kernel v8: bf16 m16n8k16 MMA, preconverted weights =========
// 128 pairs/block, 8 warps; warp owns a 16-row m-strip through both layers.
// X, W stored as bf16x2 words (hi + lo arrays), XPAD=36 => conflict-free frags.
struct PairSmem {
    unsigned Wh1[64 * XPAD], Wl1[64 * XPAD];
    unsigned Wh2[64 * XPAD], Wl2[64 * XPAD];
    unsigned Xh[128 * XPAD], Xl[128 * XPAD];
    float W3[128];                // [k][2]
    float b1[64], b2[64], b0[64], Gg[64];
    float b3[2];
    float epart[8];
};
#define PAIR_SMEM_BYTES ((int)sizeof(PairSmem))

__device__ __forceinline__ void mma_layer(unsigned* __restrict__ Xh,
                                          unsigned* __restrict__ Xl,
                                          const unsigned* __restrict__ Wh,
                                          const unsigned* __restrict__ Wl,
                                          const float* __restrict__ bias,
                                          int w, int lane) {
    int r = lane >> 2, c = lane & 3;
    float acc[8][4];
#pragma unroll
    for (int nt = 0; nt < 8; ++nt) {
        float bv0 = bias[nt * 8 + 2 * c], bv1 = bias[nt * 8 + 2 * c + 1];
        acc[nt][0] = bv0; acc[nt][1] = bv1; acc[nt][2] = bv0; acc[nt][3] = bv1;
    }
    const unsigned* XhA = Xh + (w * 16 + r) * XPAD;
    const unsigned* XhB = XhA + 8 * XPAD;
    const unsigned* XlA = Xl + (w * 16 + r) * XPAD;
    const unsigned* XlB = XlA + 8 * XPAD;
#pragma unroll
    for (int s = 0; s < 4; ++s) {
        unsigned ah[4] = {XhA[s * 8 + c], XhB[s * 8 + c],
                          XhA[s * 8 + c + 4], XhB[s * 8 + c + 4]};
        unsigned al[4] = {XlA[s * 8 + c], XlB[s * 8 + c],
                          XlA[s * 8 + c + 4], XlB[s * 8 + c + 4]};
#pragma unroll
        for (int nt = 0; nt < 8; ++nt) {
            const unsigned* wh = Wh + (nt * 8 + r) * XPAD + s * 8;
            const unsigned* wl = Wl + (nt * 8 + r) * XPAD + s * 8;
            unsigned bh[2] = {wh[c], wh[c + 4]};
            unsigned bl[2] = {wl[c], wl[c + 4]};
            mma_bf16(acc[nt], ah, bh);   // x_hi * w_hi
            mma_bf16(acc[nt], al, bh);   // x_lo * w_hi
            mma_bf16(acc[nt], ah, bl);   // x_hi * w_lo
        }
    }
    __syncwarp();   // own-strip rows only; warp-local handoff
    unsigned* XhO = Xh + (w * 16 + r) * XPAD;
    unsigned* XhO8 = XhO + 8 * XPAD;
    unsigned* XlO = Xl + (w * 16 + r) * XPAD;
    unsigned* XlO8 = XlO + 8 * XPAD;
#pragma unroll
    for (int nt = 0; nt < 8; ++nt) {
        int kw = nt * 4 + c;
        float t0 = my_tanh(acc[nt][0]), t1 = my_tanh(acc[nt][1]);
        float t2 = my_tanh(acc[nt][2]), t3 = my_tanh(acc[nt][3]);
        __nv_bfloat16 h0 = __float2bfloat16(t0), h1 = __float2bfloat16(t1);
        __nv_bfloat16 h2 = __float2bfloat16(t2), h3 = __float2bfloat16(t3);
        XhO[kw] = pack_bf(h0, h1);
        XlO[kw] = pack_bf(__float2bfloat16(t0 - __bfloat162float(h0)),
                          __float2bfloat16(t1 - __bfloat162float(h1)));
        XhO8[kw] = pack_bf(h2, h3);
        XlO8[kw] = pack_bf(__float2bfloat16(t2 - __bfloat162float(h2)),
                           __float2bfloat16(t3 - __bfloat162float(h3)));
    }
    __syncwarp();
}

__global__ __launch_bounds__(256, 2) void pair_kernel(
    const float* __restrict__ ab1, const float* __restrict__ ab2,
    const float* __restrict__ aw3, const float* __restrict__ ab3,
    const float* __restrict__ ab0, const int* __restrict__ dimp) {
    extern __shared__ __align__(16) char smem_raw[];
    PairSmem* sm = (PairSmem*)smem_raw;
    int dim = read_dim(dimp);
    int p0 = blockIdx.x * BLKP;
    if (p0 >= dim) return;               // uniform block exit
    int b = blockIdx.y, t = threadIdx.x;

    // ---- copy preconverted split-bf16 weights (4 contiguous arrays) ----
    {
        uint4* dstv = (uint4*)sm->Wh1;
#pragma unroll
        for (int i = 0; i < 9; ++i) dstv[t + 256 * i] = d_Wpre4[t + 256 * i];
        if (t < 64) {
            sm->b1[t] = ab1[t];
            sm->b2[t] = ab2[t];
            sm->b0[t] = ab0[t];
            sm->Gg[t] = d_Gg[b * 64 + t];
            sm->W3[2 * t + 0] = aw3[2 * t + 0];
            sm->W3[2 * t + 1] = aw3[2 * t + 1];
        }
        if (t < 2) sm->b3[t] = ab3[t];
    }
    __syncthreads();

    // shift SA = sum_k |W3[k][0]|  (logit part <= SA since |h| < 1)
    float SA = 0.f;
#pragma unroll
    for (int k = 0; k < 64; ++k) SA += fabsf(sm->W3[2 * k]);

    // ---- layer 0: 2 threads per pair, each builds 32 features as hi/lo words ----
    {
        int lp = t >> 1, half = t & 1;
        int p = p0 + lp;
        int cnt = d_count[b];
        int kb = half * 32;
        unsigned* xh = sm->Xh + lp * XPAD + half * 16;
        unsigned* xl = sm->Xl + lp * XPAD + half * 16;
        float v[32];
        if (p < cnt && p < dim) {
            int q = d_order[b * DIMMAX + p];
            int i1 = q / Nn, i2 = q - i1 * Nn;
            const float4* Ga = (const float4*)(d_A + ((size_t)(b * Nn + i1)) * 64 + kb);
            const float4* Cc = (const float4*)(d_C + ((size_t)(b * Nn + i2)) * 64 + kb);
#pragma unroll
            for (int kk = 0; kk < 8; ++kk) {
                float4 a = Ga[kk], c4 = Cc[kk];
                int k = kb + 4 * kk;
                v[4 * kk + 0] = my_tanh(sm->Gg[k + 0] + a.x + c4.x);
                v[4 * kk + 1] = my_tanh(sm->Gg[k + 1] + a.y + c4.y);
                v[4 * kk + 2] = my_tanh(sm->Gg[k + 2] + a.z + c4.z);
                v[4 * kk + 3] = my_tanh(sm->Gg[k + 3] + a.w + c4.w);
            }
        } else {
            // invalid / out-of-range: zeroed input -> pre-activation = b0
#pragma unroll
            for (int kk = 0; kk < 32; ++kk) v[kk] = my_tanh(sm->b0[kb + kk]);
        }
#pragma unroll
        for (int kk2 = 0; kk2 < 16; ++kk2) {
            float v0 = v[2 * kk2], v1 = v[2 * kk2 + 1];
            __nv_bfloat16 h0 = __float2bfloat16(v0), h1 = __float2bfloat16(v1);
            xh[kk2] = pack_bf(h0, h1);
            xl[kk2] = pack_bf(__float2bfloat16(v0 - __bfloat162float(h0)),
                              __float2bfloat16(v1 - __bfloat162float(h1)));
        }
    }
    __syncwarp();

    int w = t >> 5, lane = t & 31;
    mma_layer(sm->Xh, sm->Xl, sm->Wh1, sm->Wl1, sm->b1, w, lane);
    mma_layer(sm->Xh, sm->Xl, sm->Wh2, sm->Wl2, sm->b2, w, lane);

    // ---- layer 3 + block partial softmax sum ----
    float ev = 0.f;
    {
        int lp = t >> 1, half = t & 1;
        int p = p0 + lp;
        const unsigned* xh = sm->Xh + lp * XPAD + half * 16;
        const unsigned* xl = sm->Xl + lp * XPAD + half * 16;
        float lg = 0.f, bq = 0.f;
        int kb = half * 32;
#pragma unroll
        for (int kk2 = 0; kk2 < 16; ++kk2) {
            __nv_bfloat162 hh = *reinterpret_cast<const __nv_bfloat162*>(xh + kk2);
            __nv_bfloat162 ll = *reinterpret_cast<const __nv_bfloat162*>(xl + kk2);
            float h0 = __bfloat162float(hh.x) + __bfloat162float(ll.x);
            float h1 = __bfloat162float(hh.y) + __bfloat162float(ll.y);
            int k = kb + 2 * kk2;
            lg += h0 * sm->W3[2 * k + 0] + h1 * sm->W3[2 * k + 2];
            bq += h0 * sm->W3[2 * k + 1] + h1 * sm->W3[2 * k + 3];
        }
        lg += __shfl_xor_sync(0xffffffffu, lg, 1);
        bq += __shfl_xor_sync(0xffffffffu, bq, 1);
        if (half == 0 && p < dim) {
            // e = exp(logit - (b3 + SA)); softmax is shift-invariant
            float e = __expf(lg - SA);
            d_logit[b * DIMMAX + p] = e;
            d_sig[b * DIMMAX + p] = 1.0f / (1.0f + __expf(-(bq + sm->b3[1])));
            ev = e;
        }
    }
    // block-level sum of e -> atomic into d_esum[b]
#pragma unroll
    for (int o = 16; o; o >>= 1) ev += __shfl_xor_sync(0xffffffffu, ev, o);
    if (lane == 0) sm->epart[w] = ev;
    __syncthreads();
    if (t == 0) {
        float s2 = 0.f;
#pragma unroll
        for (int i = 0; i < 8; ++i) s2 += sm->epart[i];
        atomicAdd(&d_esum[b], s2);
    }
}

// ---------------- kernel 3: wide normalize + scatter ----------------
__global__ void scatter_kernel(float* __restrict__ out, const int* __restrict__ dimp) {
    int dim = read_dim(dimp);
    int b = blockIdx.y;
    int p = blockIdx.x * 256 + threadIdx.x;
    if (p >= dim) return;
    if (p >= d_count[b]) return;  // valid == 0 -> contributes zeros only
    float inv = 1.0f / d_esum[b];
    int q = d_order[b * DIMMAX + p];
    float pi = d_logit[b * DIMMAX + p] * inv;
    float sg = d_sig[b * DIMMAX + p];
    float* ob = out + (size_t)b * 20000;
    ob[q] = pi * sg;
    ob[10000 + q] = pi * (1.0f - sg);
}

// ---------------- launcher (3 launches, single stream) ----------------
extern "C" void kernel_launch(void* const* d_in, const int* in_sizes, int n_in,
                              void* d_out, int out_size) {
    const float* emb = (const float*)d_in[0];
    const int* dimp;
    int base;
    if (n_in >= 18 && in_sizes[1] == 1) {   // dict order: emb, dim, actor..., critic...
        dimp = (const int*)d_in[1];
        base = 2;
    } else {                                // signature order: emb, actor..., critic..., dim
        dimp = (const int*)d_in[n_in - 1];
        base = 1;
    }
    const float* aw0 = (const float*)d_in[base + 0];
    const float* ab0 = (const float*)d_in[base + 1];
    const float* aw1 = (const float*)d_in[base + 2];
    const float* ab1 = (const float*)d_in[base + 3];
    const float* aw2 = (const float*)d_in[base + 4];
    const float* ab2 = (const float*)d_in[base + 5];
    const float* aw3 = (const float*)d_in[base + 6];
    const float* ab3 = (const float*)d_in[base + 7];
    const float* cw0 = (const float*)d_in[base + 8];
    const float* cb0 = (const float*)d_in[base + 9];
    const float* cw1 = (const float*)d_in[base + 10];
    const float* cb1 = (const float*)d_in[base + 11];
    const float* cw2 = (const float*)d_in[base + 12];
    const float* cb2 = (const float*)d_in[base + 13];
    const float* cw3 = (const float*)d_in[base + 14];
    const float* cb3 = (const float*)d_in[base + 15];

    float* out = (float*)d_out;
    int voff = out_size - Bz;  // value slot after the filled region (expect 640000)

    static int init_done = 0;
    if (!init_done) {
        cudaFuncSetAttribute(pair_kernel, cudaFuncAttributeMaxDynamicSharedMemorySize,
                             PAIR_SMEM_BYTES);
        cudaFuncSetAttribute(prep_kernel, cudaFuncAttributeMaxDynamicSharedMemorySize,
                             PREP_SMEM);
        init_done = 1;
    }

    prep_kernel<<<dim3(Bz, 7), 256, PREP_SMEM>>>(emb, aw0, ab0, aw1, aw2,
                                                 cw0, cb0, cw1, cb1, cw2, cb2,
                                                 cw3, cb3, out, voff, dimp);
    pair_kernel<<<dim3(PBLK, Bz), 256, PAIR_SMEM_BYTES>>>(ab1, ab2, aw3, ab3,
                                                          ab0, dimp);
    scatter_kernel<<<dim3(40, Bz), 256>>>(out, dimp);
}

// round 12
// speedup vs baseline: 1.6265x; 1.0645x over previous
#include <cuda_runtime.h>
#include <cuda_bf16.h>
#include <cstdint>
#include <math.h>

#define Bz     32
#define Nn     100
#define Ff     514
#define FE     614      // 514 feats + 100 mask cols
#define ROWSE  101
#define NN2    10000
#define DIMMAX 10000
#define BLKP   128      // pairs per block in pair kernel
#define PBLK   79       // ceil(DIMMAX/128)
#define XPAD   36
#define ASTR   20       // word stride in ac GEMM smem (20 ≡ 4 mod 32 -> conflict-free)

// ---------------- scratch (static device globals; no allocation) ----------------
__device__ int   d_order[Bz * DIMMAX];
__device__ int   d_count[Bz];
__device__ float d_Gg[Bz * 64];
__device__ float d_A[Bz * Nn * 64];
__device__ float d_C[Bz * Nn * 64];
__device__ float d_logit[Bz * DIMMAX];   // holds e = exp(logit - shift)
__device__ float d_sig[Bz * DIMMAX];
__device__ float d_esum[Bz];
__device__ uint4 d_Wpre4[2304];          // pair weights, split-bf16 padded layout

// ---------------- small helpers ----------------
__device__ __forceinline__ int read_dim(const int* p) {
    int v = *p;
    if (v < 1 || v > DIMMAX) {            // safety: tolerate float-encoded scalar
        float f = __int_as_float(v);
        v = (int)f;
    }
    if (v < 0) v = 0;
    if (v > DIMMAX) v = DIMMAX;
    return v;
}

// Eigen-style rational minimax tanh: 1 MUFU (rcp) instead of 2 (ex2+rcp).
__device__ __forceinline__ float my_tanh(float x) {
    x = fminf(fmaxf(x, -7.90531110763549805f), 7.90531110763549805f);
    float x2 = x * x;
    float p = fmaf(x2, -2.76076847742355e-16f, 2.00018790482477e-13f);
    p = fmaf(x2, p, -8.60467152213735e-11f);
    p = fmaf(x2, p, 5.12229709037114e-08f);
    p = fmaf(x2, p, 1.48572235717979e-05f);
    p = fmaf(x2, p, 6.37261928875436e-04f);
    p = fmaf(x2, p, 4.89352455891786e-03f);
    p = x * p;
    float q = fmaf(x2, 1.19825839466702e-06f, 1.18534705686654e-04f);
    q = fmaf(x2, q, 2.26843463243900e-03f);
    q = fmaf(x2, q, 4.89352518554385e-03f);
    return __fdividef(p, q);
}

__device__ __forceinline__ unsigned pack_bf(__nv_bfloat16 a, __nv_bfloat16 b) {
    __nv_bfloat162 v;
    v.x = a;  // low half
    v.y = b;  // high half
    return *reinterpret_cast<unsigned*>(&v);
}

__device__ __forceinline__ void split_word(float a, float b, unsigned& hw, unsigned& lw) {
    __nv_bfloat16 ha = __float2bfloat16(a), hb = __float2bfloat16(b);
    hw = pack_bf(ha, hb);
    lw = pack_bf(__float2bfloat16(a - __bfloat162float(ha)),
                 __float2bfloat16(b - __bfloat162float(hb)));
}

__device__ __forceinline__ void mma_bf16(float (&d)[4], const unsigned (&a)[4],
                                         const unsigned (&b)[2]) {
    asm volatile(
        "mma.sync.aligned.m16n8k16.row.col.f32.bf16.bf16.f32 "
        "{%0,%1,%2,%3}, {%4,%5,%6,%7}, {%8,%9}, {%0,%1,%2,%3};"
        : "+f"(d[0]), "+f"(d[1]), "+f"(d[2]), "+f"(d[3])
        : "r"(a[0]), "r"(a[1]), "r"(a[2]), "r"(a[3]), "r"(b[0]), "r"(b[1]));
}

// ================= prep kernel: flat 146 blocks: ac(50)/scan(32)/head(32)/zero(32)
// ac dynamic smem: 2 buffers x (128 W + 64 A rows) x 20 words x 2 (hi,lo) = 61440B
#define PREP_SMEM (2 * (128 + 64) * 2 * ASTR * 4)

__device__ void scan_role(const float* __restrict__ emb, int b, int dim, char* sh) {
    int t = threadIdx.x;           // 256
    int lane = t & 31, w = t >> 5; // 8 warps
    unsigned* bal = (unsigned*)sh;         // [320]
    int* pre = (int*)(sh + 320 * 4);       // [320]
    // phase 1: batched loads (20 in flight), then ballots
#pragma unroll
    for (int hf = 0; hf < 2; ++hf) {
        float v[20];
#pragma unroll
        for (int c2 = 0; c2 < 20; ++c2) {
            int c = hf * 20 + c2;
            int idx = c * 256 + t;
            float val = 0.f;
            if (idx < NN2) {
                int i = idx / Nn, j = idx - i * Nn;
                val = emb[(size_t)(b * ROWSE + 1 + i) * FE + Ff + j];
            }
            v[c2] = val;
        }
#pragma unroll
        for (int c2 = 0; c2 < 20; ++c2) {
            unsigned bl = __ballot_sync(0xffffffffu, v[c2] > 0.5f);
            if (lane == 0) bal[(hf * 20 + c2) * 8 + w] = bl;
        }
    }
    __syncthreads();
    if (t < 32) {
        int loc[10];
        int s = 0;
#pragma unroll
        for (int k = 0; k < 10; ++k) {
            int v = __popc(bal[lane * 10 + k]);
            loc[k] = s;
            s += v;
        }
        int p = s;
#pragma unroll
        for (int o = 1; o < 32; o <<= 1) {
            int n = __shfl_up_sync(0xffffffffu, p, o);
            if (lane >= o) p += n;
        }
        int off = p - s;
#pragma unroll
        for (int k = 0; k < 10; ++k) pre[lane * 10 + k] = off + loc[k];
        if (lane == 31) d_count[b] = p;
    }
    __syncthreads();
#pragma unroll
    for (int c = 0; c < 40; ++c) {
        unsigned bl = bal[c * 8 + w];
        if ((bl >> lane) & 1u) {
            int rank = pre[c * 8 + w] + __popc(bl & ((1u << lane) - 1u));
            if (rank < dim) d_order[b * DIMMAX + rank] = c * 256 + t;
        }
    }
}

__device__ void head_role(const float* __restrict__ emb,
                          const float* __restrict__ aw0, const float* __restrict__ ab0,
                          const float* __restrict__ cw0, const float* __restrict__ cb0,
                          const float* __restrict__ cw1, const float* __restrict__ cb1,
                          const float* __restrict__ cw2, const float* __restrict__ cb2,
                          const float* __restrict__ cw3, const float* __restrict__ cb3,
                          float* __restrict__ out, int voff, int b, char* sh) {
    float* row = (float*)sh;              // [516]
    float* part = row + 516;              // [256]
    float* ha = part + 256;               // [64]
    float* hb = ha + 64;                  // [64]
    int t = threadIdx.x;                  // 256
    for (int k = t; k < Ff; k += 256) row[k] = emb[(size_t)b * ROWSE * FE + k];
    __syncthreads();
    int j = t & 63, ks = t >> 6;  // 4-way k split
    {
        float acc = 0.f;
        for (int k = ks; k < Ff; k += 4) acc += row[k] * aw0[(size_t)k * 64 + j];
        part[t] = acc;
    }
    __syncthreads();
    if (t < 64) {
        float s = ab0[j] + part[j] + part[64 + j] + part[128 + j] + part[192 + j];
        d_Gg[b * 64 + j] = s;
    }
    __syncthreads();
    {
        float acc = 0.f;
        for (int k = ks; k < Ff; k += 4) acc += row[k] * cw0[(size_t)k * 64 + j];
        part[t] = acc;
    }
    __syncthreads();
    if (t < 64) {
        float s = cb0[j] + part[j] + part[64 + j] + part[128 + j] + part[192 + j];
        ha[j] = my_tanh(s);
    }
    __syncthreads();
    if (t < 64) {
        float acc = cb1[t];
        for (int k = 0; k < 64; ++k) acc += ha[k] * cw1[k * 64 + t];
        hb[t] = my_tanh(acc);
    }
    __syncthreads();
    if (t < 64) {
        float acc = cb2[t];
        for (int k = 0; k < 64; ++k) acc += hb[k] * cw2[k * 64 + t];
        ha[t] = my_tanh(acc);
    }
    __syncthreads();
    if (t == 0) {
        float v = cb3[0];
        for (int k = 0; k < 64; ++k) v += ha[k] * cw3[k];
        out[voff + b] = v;
    }
}

// [A|C] = nodes[3200,514] @ [W0_A | W0_C], bf16 3-term split tensor-core GEMM.
// 64-row x 128-col tiles (50 blocks), K padded 514 -> 544 (17 x k32 chunks).
__device__ void ac_mma_role(const float* __restrict__ emb,
                            const float* __restrict__ w0, int blk, char* sh) {
    int t = threadIdx.x;   // 256
    unsigned* buf = (unsigned*)sh;
    const int BUFW = (128 + 64) * 2 * ASTR;        // 7680 words per buffer
    const float* wA = w0 + (size_t)Ff * 64;        // A weights [514][64]
    const float* wC = wA + (size_t)Ff * 64;        // C weights [514][64]
    int m0 = blk * 64;

    // A staging: row = t>>2 (0..63), q = t&3 (4 threads/row, 4 words each)
    int arow = t >> 2, q = t & 3;
    int gr = m0 + arow;
    int bb = gr / Nn, node = gr - bb * Nn;
    const float* asrc = emb + (size_t)(bb * ROWSE + 1 + node) * FE;

    float wreg[16];
    float areg[8];

#define ACL(kb)                                                              \
    do {                                                                     \
        _Pragma("unroll") for (int i = 0; i < 8; ++i) {                      \
            int e = t + 256 * i;                                             \
            int n = e & 127, wd = e >> 7;                                    \
            int k0 = (kb) + 2 * wd;                                          \
            const float* src = (n < 64) ? (wA + n) : (wC + (n - 64));        \
            wreg[2 * i] = (k0 < Ff) ? src[(size_t)k0 * 64] : 0.f;            \
            wreg[2 * i + 1] = (k0 + 1 < Ff) ? src[(size_t)(k0 + 1) * 64] : 0.f; \
        }                                                                    \
        _Pragma("unroll") for (int jj = 0; jj < 4; ++jj) {                   \
            int ka = (kb) + 8 * q + 2 * jj;                                  \
            float2 v2 = make_float2(0.f, 0.f);                               \
            if (ka < Ff) {                                                   \
                v2 = *(const float2*)(asrc + ka);                            \
                if (ka + 1 >= Ff) v2.y = 0.f;                                \
            }                                                                \
            areg[2 * jj] = v2.x;                                             \
            areg[2 * jj + 1] = v2.y;                                         \
        }                                                                    \
    } while (0)

#define ACS(dst)                                                             \
    do {                                                                     \
        unsigned* Wh_ = (dst);                                               \
        unsigned* Wl_ = Wh_ + 128 * ASTR;                                    \
        unsigned* Ah_ = Wl_ + 128 * ASTR;                                    \
        unsigned* Al_ = Ah_ + 64 * ASTR;                                     \
        _Pragma("unroll") for (int i = 0; i < 8; ++i) {                      \
            int e = t + 256 * i;                                             \
            int n = e & 127, wd = e >> 7;                                    \
            unsigned hw, lw;                                                 \
            split_word(wreg[2 * i], wreg[2 * i + 1], hw, lw);                \
            Wh_[n * ASTR + wd] = hw;                                         \
            Wl_[n * ASTR + wd] = lw;                                         \
        }                                                                    \
        _Pragma("unroll") for (int jj = 0; jj < 4; ++jj) {                   \
            unsigned hw, lw;                                                 \
            split_word(areg[2 * jj], areg[2 * jj + 1], hw, lw);              \
            Ah_[arow * ASTR + q * 4 + jj] = hw;                              \
            Al_[arow * ASTR + q * 4 + jj] = lw;                              \
        }                                                                    \
    } while (0)

    ACL(0);
    ACS(buf);
    ACL(32);   // regs now hold chunk 1
    __syncthreads();

    int w = t >> 5, lane = t & 31;
    int r = lane >> 2, c = lane & 3;
    int ms = (w & 3) * 16;       // m-strip base within 64-row tile
    int ng = (w >> 2) * 64;      // n-group base (8 n8 tiles)

    float acc[8][4];
#pragma unroll
    for (int nt = 0; nt < 8; ++nt)
#pragma unroll
        for (int i2 = 0; i2 < 4; ++i2) acc[nt][i2] = 0.f;

    for (int kc = 0; kc < 17; ++kc) {
        unsigned* cur = buf + (kc & 1) * BUFW;
        unsigned* alt = buf + ((kc & 1) ^ 1) * BUFW;
        const unsigned* Wh = cur;
        const unsigned* Wl = Wh + 128 * ASTR;
        const unsigned* Ah = Wl + 128 * ASTR;
        const unsigned* Al = Ah + 64 * ASTR;
#pragma unroll
        for (int s2 = 0; s2 < 2; ++s2) {
            int kwb = s2 * 8;
            const unsigned* aha = Ah + (ms + r) * ASTR + kwb;
            const unsigned* ala = Al + (ms + r) * ASTR + kwb;
            unsigned ah[4] = {aha[c], aha[8 * ASTR + c], aha[c + 4], aha[8 * ASTR + c + 4]};
            unsigned al[4] = {ala[c], ala[8 * ASTR + c], ala[c + 4], ala[8 * ASTR + c + 4]};
#pragma unroll
            for (int nt = 0; nt < 8; ++nt) {
                const unsigned* wh = Wh + (ng + nt * 8 + r) * ASTR + kwb;
                const unsigned* wl = Wl + (ng + nt * 8 + r) * ASTR + kwb;
                unsigned bh[2] = {wh[c], wh[c + 4]};
                unsigned bl[2] = {wl[c], wl[c + 4]};
                mma_bf16(acc[nt], ah, bh);   // a_hi * w_hi
                mma_bf16(acc[nt], al, bh);   // a_lo * w_hi
                mma_bf16(acc[nt], ah, bl);   // a_hi * w_lo
            }
        }
        if (kc < 16) {
            ACS(alt);                            // store chunk kc+1
            if (kc < 15) ACL((kc + 2) * 32);     // load chunk kc+2
        }
        __syncthreads();
    }
#undef ACL
#undef ACS

    // epilogue: fp32 results -> d_A / d_C
#pragma unroll
    for (int nt = 0; nt < 8; ++nt) {
        int j = ng + nt * 8 + 2 * c;
        int gr0 = m0 + ms + r, gr1 = gr0 + 8;
        float* dst = (j < 64) ? d_A : d_C;
        int jj = (j < 64) ? j : j - 64;
        *(float2*)(dst + (size_t)gr0 * 64 + jj) = make_float2(acc[nt][0], acc[nt][1]);
        *(float2*)(dst + (size_t)gr1 * 64 + jj) = make_float2(acc[nt][2], acc[nt][3]);
    }
}

// zero output slab + esum, and convert this block's slice of pair weights
__device__ void zero_role(float* __restrict__ out, int b,
                          const float* __restrict__ aw1,
                          const float* __restrict__ aw2) {
    float4 z = make_float4(0.f, 0.f, 0.f, 0.f);
    float4* ob = (float4*)(out + (size_t)b * 20000);
    int t = threadIdx.x;
    for (int i = t; i < 5000; i += 256) ob[i] = z;
    if (t == 0) d_esum[b] = 0.f;
    // convert slice: elements e in [b*128, b*128+128) of aw1 and aw2
    if (t < 128) {
        __nv_bfloat16* wp = (__nv_bfloat16*)d_Wpre4;
        int e = b * 128 + t;
        int k = e >> 6, n = e & 63;
        int ei = n * 72 + k;
        float w1v = aw1[e], w2v = aw2[e];
        __nv_bfloat16 h1 = __float2bfloat16(w1v);
        wp[0 * 4608 + ei] = h1;
        wp[1 * 4608 + ei] = __float2bfloat16(w1v - __bfloat162float(h1));
        __nv_bfloat16 h2 = __float2bfloat16(w2v);
        wp[2 * 4608 + ei] = h2;
        wp[3 * 4608 + ei] = __float2bfloat16(w2v - __bfloat162float(h2));
    }
}

__global__ void prep_kernel(const float* __restrict__ emb,
                            const float* __restrict__ aw0, const float* __restrict__ ab0,
                            const float* __restrict__ aw1, const float* __restrict__ aw2,
                            const float* __restrict__ cw0, const float* __restrict__ cb0,
                            const float* __restrict__ cw1, const float* __restrict__ cb1,
                            const float* __restrict__ cw2, const float* __restrict__ cb2,
                            const float* __restrict__ cw3, const float* __restrict__ cb3,
                            float* __restrict__ out, int voff,
                            const int* __restrict__ dimp) {
    extern __shared__ __align__(16) char sh[];
    int bid = blockIdx.x;
    if (bid < 50) {
        ac_mma_role(emb, aw0, bid, sh);
    } else if (bid < 82) {
        scan_role(emb, bid - 50, read_dim(dimp), sh);
    } else if (bid < 114) {
        head_role(emb, aw0, ab0, cw0, cb0, cw1, cb1, cw2, cb2, cw3, cb3,
                  out, voff, bid - 82, sh);
    } else {
        zero_role(out, bid - 114, aw1, aw2);
    }
}

// ============== pair kernel v8: bf16 m16n8k16 MMA, preconverted weights =========
// 128 pairs/block, 8 warps; warp owns a 16-row m-strip through both layers.
// X, W stored as bf16x2 words (hi + lo arrays), XPAD=36 => conflict-free frags.
struct PairSmem {
    unsigned Wh1[64 * XPAD], Wl1[64 * XPAD];
    unsigned Wh2[64 * XPAD], Wl2[64 * XPAD];
    unsigned Xh[128 * XPAD], Xl[128 * XPAD];
    float W3[128];                // [k][2]
    float b1[64], b2[64], b0[64], Gg[64];
    float b3[2];
    float epart[8];
};
#define PAIR_SMEM_BYTES ((int)sizeof(PairSmem))

__device__ __forceinline__ void mma_layer(unsigned* __restrict__ Xh,
                                          unsigned* __restrict__ Xl,
                                          const unsigned* __restrict__ Wh,
                                          const unsigned* __restrict__ Wl,
                                          const float* __restrict__ bias,
                                          int w, int lane) {
    int r = lane >> 2, c = lane & 3;
    float acc[8][4];
#pragma unroll
    for (int nt = 0; nt < 8; ++nt) {
        float bv0 = bias[nt * 8 + 2 * c], bv1 = bias[nt * 8 + 2 * c + 1];
        acc[nt][0] = bv0; acc[nt][1] = bv1; acc[nt][2] = bv0; acc[nt][3] = bv1;
    }
    const unsigned* XhA = Xh + (w * 16 + r) * XPAD;
    const unsigned* XhB = XhA + 8 * XPAD;
    const unsigned* XlA = Xl + (w * 16 + r) * XPAD;
    const unsigned* XlB = XlA + 8 * XPAD;
#pragma unroll
    for (int s = 0; s < 4; ++s) {
        unsigned ah[4] = {XhA[s * 8 + c], XhB[s * 8 + c],
                          XhA[s * 8 + c + 4], XhB[s * 8 + c + 4]};
        unsigned al[4] = {XlA[s * 8 + c], XlB[s * 8 + c],
                          XlA[s * 8 + c + 4], XlB[s * 8 + c + 4]};
#pragma unroll
        for (int nt = 0; nt < 8; ++nt) {
            const unsigned* wh = Wh + (nt * 8 + r) * XPAD + s * 8;
            const unsigned* wl = Wl + (nt * 8 + r) * XPAD + s * 8;
            unsigned bh[2] = {wh[c], wh[c + 4]};
            unsigned bl[2] = {wl[c], wl[c + 4]};
            mma_bf16(acc[nt], ah, bh);   // x_hi * w_hi
            mma_bf16(acc[nt], al, bh);   // x_lo * w_hi
            mma_bf16(acc[nt], ah, bl);   // x_hi * w_lo
        }
    }
    __syncwarp();   // own-strip rows only; warp-local handoff
    unsigned* XhO = Xh + (w * 16 + r) * XPAD;
    unsigned* XhO8 = XhO + 8 * XPAD;
    unsigned* XlO = Xl + (w * 16 + r) * XPAD;
    unsigned* XlO8 = XlO + 8 * XPAD;
#pragma unroll
    for (int nt = 0; nt < 8; ++nt) {
        int kw = nt * 4 + c;
        float t0 = my_tanh(acc[nt][0]), t1 = my_tanh(acc[nt][1]);
        float t2 = my_tanh(acc[nt][2]), t3 = my_tanh(acc[nt][3]);
        __nv_bfloat16 h0 = __float2bfloat16(t0), h1 = __float2bfloat16(t1);
        __nv_bfloat16 h2 = __float2bfloat16(t2), h3 = __float2bfloat16(t3);
        XhO[kw] = pack_bf(h0, h1);
        XlO[kw] = pack_bf(__float2bfloat16(t0 - __bfloat162float(h0)),
                          __float2bfloat16(t1 - __bfloat162float(h1)));
        XhO8[kw] = pack_bf(h2, h3);
        XlO8[kw] = pack_bf(__float2bfloat16(t2 - __bfloat162float(h2)),
                           __float2bfloat16(t3 - __bfloat162float(h3)));
    }
    __syncwarp();
}

__global__ __launch_bounds__(256, 3) void pair_kernel(
    const float* __restrict__ ab1, const float* __restrict__ ab2,
    const float* __restrict__ aw3, const float* __restrict__ ab3,
    const float* __restrict__ ab0, const int* __restrict__ dimp) {
    extern __shared__ __align__(16) char smem_raw[];
    PairSmem* sm = (PairSmem*)smem_raw;
    int dim = read_dim(dimp);
    int p0 = blockIdx.x * BLKP;
    if (p0 >= dim) return;               // uniform block exit
    int b = blockIdx.y, t = threadIdx.x;

    // ---- copy preconverted split-bf16 weights (4 contiguous arrays) ----
    {
        uint4* dstv = (uint4*)sm->Wh1;
#pragma unroll
        for (int i = 0; i < 9; ++i) dstv[t + 256 * i] = d_Wpre4[t + 256 * i];
        if (t < 64) {
            sm->b1[t] = ab1[t];
            sm->b2[t] = ab2[t];
            sm->b0[t] = ab0[t];
            sm->Gg[t] = d_Gg[b * 64 + t];
            sm->W3[2 * t + 0] = aw3[2 * t + 0];
            sm->W3[2 * t + 1] = aw3[2 * t + 1];
        }
        if (t < 2) sm->b3[t] = ab3[t];
    }
    __syncthreads();

    // shift SA = sum_k |W3[k][0]|  (logit part <= SA since |h| < 1)
    float SA = 0.f;
#pragma unroll
    for (int k = 0; k < 64; ++k) SA += fabsf(sm->W3[2 * k]);

    // ---- layer 0: 2 threads per pair, each builds 32 features as hi/lo words ----
    {
        int lp = t >> 1, half = t & 1;
        int p = p0 + lp;
        int cnt = d_count[b];
        int kb = half * 32;
        unsigned* xh = sm->Xh + lp * XPAD + half * 16;
        unsigned* xl = sm->Xl + lp * XPAD + half * 16;
        float v[32];
        if (p < cnt && p < dim) {
            int q = d_order[b * DIMMAX + p];
            int i1 = q / Nn, i2 = q - i1 * Nn;
            const float4* Ga = (const float4*)(d_A + ((size_t)(b * Nn + i1)) * 64 + kb);
            const float4* Cc = (const float4*)(d_C + ((size_t)(b * Nn + i2)) * 64 + kb);
#pragma unroll
            for (int kk = 0; kk < 8; ++kk) {
                float4 a = Ga[kk], c4 = Cc[kk];
                int k = kb + 4 * kk;
                v[4 * kk + 0] = my_tanh(sm->Gg[k + 0] + a.x + c4.x);
                v[4 * kk + 1] = my_tanh(sm->Gg[k + 1] + a.y + c4.y);
                v[4 * kk + 2] = my_tanh(sm->Gg[k + 2] + a.z + c4.z);
                v[4 * kk + 3] = my_tanh(sm->Gg[k + 3] + a.w + c4.w);
            }
        } else {
            // invalid / out-of-range: zeroed input -> pre-activation = b0
#pragma unroll
            for (int kk = 0; kk < 32; ++kk) v[kk] = my_tanh(sm->b0[kb + kk]);
        }
#pragma unroll
        for (int kk2 = 0; kk2 < 16; ++kk2) {
            float v0 = v[2 * kk2], v1 = v[2 * kk2 + 1];
            __nv_bfloat16 h0 = __float2bfloat16(v0), h1 = __float2bfloat16(v1);
            xh[kk2] = pack_bf(h0, h1);
            xl[kk2] = pack_bf(__float2bfloat16(v0 - __bfloat162float(h0)),
                              __float2bfloat16(v1 - __bfloat162float(h1)));
        }
    }
    __syncwarp();

    int w = t >> 5, lane = t & 31;
    mma_layer(sm->Xh, sm->Xl, sm->Wh1, sm->Wl1, sm->b1, w, lane);
    mma_layer(sm->Xh, sm->Xl, sm->Wh2, sm->Wl2, sm->b2, w, lane);

    // ---- layer 3 + block partial softmax sum ----
    float ev = 0.f;
    {
        int lp = t >> 1, half = t & 1;
        int p = p0 + lp;
        const unsigned* xh = sm->Xh + lp * XPAD + half * 16;
        const unsigned* xl = sm->Xl + lp * XPAD + half * 16;
        float lg = 0.f, bq = 0.f;
        int kb = half * 32;
#pragma unroll
        for (int kk2 = 0; kk2 < 16; ++kk2) {
            __nv_bfloat162 hh = *reinterpret_cast<const __nv_bfloat162*>(xh + kk2);
            __nv_bfloat162 ll = *reinterpret_cast<const __nv_bfloat162*>(xl + kk2);
            float h0 = __bfloat162float(hh.x) + __bfloat162float(ll.x);
            float h1 = __bfloat162float(hh.y) + __bfloat162float(ll.y);
            int k = kb + 2 * kk2;
            lg += h0 * sm->W3[2 * k + 0] + h1 * sm->W3[2 * k + 2];
            bq += h0 * sm->W3[2 * k + 1] + h1 * sm->W3[2 * k + 3];
        }
        lg += __shfl_xor_sync(0xffffffffu, lg, 1);
        bq += __shfl_xor_sync(0xffffffffu, bq, 1);
        if (half == 0 && p < dim) {
            // e = exp(logit - (b3 + SA)); softmax is shift-invariant
            float e = __expf(lg - SA);
            d_logit[b * DIMMAX + p] = e;
            d_sig[b * DIMMAX + p] = 1.0f / (1.0f + __expf(-(bq + sm->b3[1])));
            ev = e;
        }
    }
    // block-level sum of e -> atomic into d_esum[b]
#pragma unroll
    for (int o = 16; o; o >>= 1) ev += __shfl_xor_sync(0xffffffffu, ev, o);
    if (lane == 0) sm->epart[w] = ev;
    __syncthreads();
    if (t == 0) {
        float s2 = 0.f;
#pragma unroll
        for (int i = 0; i < 8; ++i) s2 += sm->epart[i];
        atomicAdd(&d_esum[b], s2);
    }
}

// ---------------- kernel 3: wide normalize + scatter ----------------
__global__ void scatter_kernel(float* __restrict__ out, const int* __restrict__ dimp) {
    int dim = read_dim(dimp);
    int b = blockIdx.y;
    int p = blockIdx.x * 256 + threadIdx.x;
    if (p >= dim) return;
    if (p >= d_count[b]) return;  // valid == 0 -> contributes zeros only
    float inv = 1.0f / d_esum[b];
    int q = d_order[b * DIMMAX + p];
    float pi = d_logit[b * DIMMAX + p] * inv;
    float sg = d_sig[b * DIMMAX + p];
    float* ob = out + (size_t)b * 20000;
    ob[q] = pi * sg;
    ob[10000 + q] = pi * (1.0f - sg);
}

// ---------------- launcher (3 launches, single stream) ----------------
extern "C" void kernel_launch(void* const* d_in, const int* in_sizes, int n_in,
                              void* d_out, int out_size) {
    const float* emb = (const float*)d_in[0];
    const int* dimp;
    int base;
    if (n_in >= 18 && in_sizes[1] == 1) {   // dict order: emb, dim, actor..., critic...
        dimp = (const int*)d_in[1];
        base = 2;
    } else {                                // signature order: emb, actor..., critic..., dim
        dimp = (const int*)d_in[n_in - 1];
        base = 1;
    }
    const float* aw0 = (const float*)d_in[base + 0];
    const float* ab0 = (const float*)d_in[base + 1];
    const float* aw1 = (const float*)d_in[base + 2];
    const float* ab1 = (const float*)d_in[base + 3];
    const float* aw2 = (const float*)d_in[base + 4];
    const float* ab2 = (const float*)d_in[base + 5];
    const float* aw3 = (const float*)d_in[base + 6];
    const float* ab3 = (const float*)d_in[base + 7];
    const float* cw0 = (const float*)d_in[base + 8];
    const float* cb0 = (const float*)d_in[base + 9];
    const float* cw1 = (const float*)d_in[base + 10];
    const float* cb1 = (const float*)d_in[base + 11];
    const float* cw2 = (const float*)d_in[base + 12];
    const float* cb2 = (const float*)d_in[base + 13];
    const float* cw3 = (const float*)d_in[base + 14];
    const float* cb3 = (const float*)d_in[base + 15];

    float* out = (float*)d_out;
    int voff = out_size - Bz;  // value slot after the filled region (expect 640000)

    static int init_done = 0;
    if (!init_done) {
        cudaFuncSetAttribute(pair_kernel, cudaFuncAttributeMaxDynamicSharedMemorySize,
                             PAIR_SMEM_BYTES);
        cudaFuncSetAttribute(prep_kernel, cudaFuncAttributeMaxDynamicSharedMemorySize,
                             PREP_SMEM);
        init_done = 1;
    }

    prep_kernel<<<146, 256, PREP_SMEM>>>(emb, aw0, ab0, aw1, aw2,
                                         cw0, cb0, cw1, cb1, cw2, cb2,
                                         cw3, cb3, out, voff, dimp);
    pair_kernel<<<dim3(PBLK, Bz), 256, PAIR_SMEM_BYTES>>>(ab1, ab2, aw3, ab3,
                                                          ab0, dimp);
    scatter_kernel<<<dim3(40, Bz), 256>>>(out, dimp);
}